// round 6
// baseline (speedup 1.0000x reference)
#include <cuda_runtime.h>
#include <math.h>

#define Bb   32
#define Ll   512
#define Hh   256
#define EMB  300
#define NH   8
#define HD   32
#define L1   513
#define NITER 6

typedef unsigned long long ull;

// packed f32x2 FMA: c = a*b + c (per 32-bit half)
#define FFMA2(c, a, b) \
    asm("fma.rn.f32x2 %0, %1, %2, %0;" : "+l"(c) : "l"(a), "l"(b))

// ------------------------- scratch (static, no allocs) -------------------------
__device__ float g_x0 [Bb*Ll*Hh];   // nodes
__device__ float g_ln [Bb*Ll*Hh];
__device__ float g_q  [Bb*Ll*Hh];
__device__ float g_k  [Bb*Ll*Hh];
__device__ float g_att[Bb*Ll*Hh];
__device__ float g_k2 [Bb*L1*Hh];
__device__ float g_v2 [Bb*L1*Hh];
__device__ float g_relay[Bb*Hh];
__device__ float g_ak [Bb*Hh];
__device__ float g_av [Bb*Hh];
__device__ float g_q2 [Bb*Hh];
__device__ float g_att2[Bb*Hh];

// ------------------------- embedding: x0 = emb[data]@W + b + pos ---------------
__global__ __launch_bounds__(256) void embed_k(
    const int* __restrict__ data, const float* __restrict__ emb,
    const float* __restrict__ W, const float* __restrict__ bias,
    const float* __restrict__ pos, float* __restrict__ x0)
{
    __shared__ float As[32][EMB];
    __shared__ int   toks[32];
    const int r0 = blockIdx.x * 32;
    const int t  = threadIdx.x;
    if (t < 32) toks[t] = data[r0 + t];
    __syncthreads();
    for (int i = t; i < 32 * EMB; i += 256) {
        int r = i / EMB, e = i - r * EMB;
        As[r][e] = emb[toks[r] * EMB + e];
    }
    __syncthreads();
    float acc[32];
    #pragma unroll
    for (int r = 0; r < 32; r++) acc[r] = 0.f;
    for (int e = 0; e < EMB; e++) {
        float w = W[e * Hh + t];
        #pragma unroll
        for (int r = 0; r < 32; r++) acc[r] += As[r][e] * w;
    }
    const float bs = bias[t];
    #pragma unroll
    for (int r = 0; r < 32; r++) {
        int row = r0 + r;
        int l   = row & (Ll - 1);
        x0[row * Hh + t] = acc[r] + bs + pos[l * Hh + t];
    }
}

// ------------------------- relay init: mean over L -----------------------------
__global__ __launch_bounds__(256) void relay_init_k(
    const float* __restrict__ x0, float* __restrict__ relay)
{
    const int b = blockIdx.x, t = threadIdx.x;
    float s = 0.f;
    for (int l = 0; l < Ll; l++) s += x0[(b * Ll + l) * Hh + t];
    relay[b * Hh + t] = s * (1.f / Ll);
}

// ------------------------- layernorm over H=256 --------------------------------
__global__ __launch_bounds__(256) void ln_k(
    const float* __restrict__ x, const float* __restrict__ g,
    const float* __restrict__ b, float* __restrict__ out)
{
    const int row = blockIdx.x, t = threadIdx.x;
    float v = x[row * Hh + t];
    float s = v;
    #pragma unroll
    for (int o = 16; o; o >>= 1) s += __shfl_xor_sync(0xffffffffu, s, o);
    __shared__ float red1[8], red2[8];
    if ((t & 31) == 0) red1[t >> 5] = s;
    __syncthreads();
    float tot = 0.f;
    #pragma unroll
    for (int w = 0; w < 8; w++) tot += red1[w];
    const float mu = tot * (1.f / Hh);
    float dv = v - mu;
    float s2 = dv * dv;
    #pragma unroll
    for (int o = 16; o; o >>= 1) s2 += __shfl_xor_sync(0xffffffffu, s2, o);
    if ((t & 31) == 0) red2[t >> 5] = s2;
    __syncthreads();
    float vtot = 0.f;
    #pragma unroll
    for (int w = 0; w < 8; w++) vtot += red2[w];
    const float var = vtot * (1.f / Hh);
    out[row * Hh + t] = g[t] * dv * rsqrtf(var + 1e-5f) + b[t];
}

// ------------------------- FFMA2 GEMM ------------------------------------------
// C[M,256] = A[M,256] @ W[256,256] + bias
// Tile: BM=128 x BN=128 x BK=16, 256 threads, 8x8 per thread as 4 row-pair f32x2.
// MODE 0: store.  MODE 1: C += leaky_relu(.)
// GATHER : A row l1==0 per batch comes from relay, else nodes (y = [relay;nodes])
// DUAL   : blockIdx.y in 0..3 -> {W0 half0, W0 half1, W1 half0, W1 half1}
#define BK 16
template <int MODE, int GATHER, int DUAL>
__global__ __launch_bounds__(256, 2) void gemm_f2(
    const float* __restrict__ A,
    const float* __restrict__ relay, const float* __restrict__ nodes,
    const float* __restrict__ W0, const float* __restrict__ b0, float* __restrict__ C0,
    const float* __restrict__ W1, const float* __restrict__ b1, float* __restrict__ C1,
    int M)
{
    __shared__ float As [BK][128];   // transposed A tile
    __shared__ float Bs2[BK][256];   // W tile,每value duplicated (2n, 2n+1)

    const int t  = threadIdx.x;
    const int ny = blockIdx.y;
    const float* W;  const float* bias;  float* C;
    if (DUAL && ny >= 2) { W = W1; bias = b1; C = C1; }
    else                 { W = W0; bias = b0; C = C0; }
    const int n0 = (DUAL ? (ny & 1) : ny) * 128;
    const int m0 = blockIdx.x * 128;

    const int tx = t & 15;          // col group: 8 cols at n0 + tx*8
    const int ty = t >> 4;          // row group: 8 rows at m0 + ty*8
    const int ar = t >> 1;          // A-load row 0..127
    const int ac = (t & 1) * 8;     // A-load col 0 or 8
    const int wr = t >> 4;          // W-load row 0..15
    const int wc = (t & 15) * 8;    // W-load col 0..120

    // hoisted A row pointer (gather resolved once)
    const int arow = m0 + ar;
    const bool rowok = arow < M;
    const float* Arow;
    if (GATHER) {
        const int b  = arow / L1;
        const int l1 = arow - b * L1;
        Arow = (l1 == 0) ? (relay + b * Hh) : (nodes + (b * Ll + l1 - 1) * Hh);
    } else {
        Arow = A + arow * Hh;
    }

    ull acc[4][8];
    #pragma unroll
    for (int i = 0; i < 4; i++)
        #pragma unroll
        for (int j = 0; j < 8; j++) acc[i][j] = 0ull;

    for (int kt = 0; kt < 256; kt += BK) {
        if (rowok) {
            float4 a0 = *reinterpret_cast<const float4*>(Arow + kt + ac);
            float4 a1 = *reinterpret_cast<const float4*>(Arow + kt + ac + 4);
            As[ac + 0][ar] = a0.x; As[ac + 1][ar] = a0.y;
            As[ac + 2][ar] = a0.z; As[ac + 3][ar] = a0.w;
            As[ac + 4][ar] = a1.x; As[ac + 5][ar] = a1.y;
            As[ac + 6][ar] = a1.z; As[ac + 7][ar] = a1.w;
        } else {
            #pragma unroll
            for (int i = 0; i < 8; i++) As[ac + i][ar] = 0.f;
        }
        {
            const float* wp = W + (kt + wr) * 256 + n0 + wc;
            float4 w0 = *reinterpret_cast<const float4*>(wp);
            float4 w1 = *reinterpret_cast<const float4*>(wp + 4);
            *reinterpret_cast<float4*>(&Bs2[wr][2*wc +  0]) = make_float4(w0.x, w0.x, w0.y, w0.y);
            *reinterpret_cast<float4*>(&Bs2[wr][2*wc +  4]) = make_float4(w0.z, w0.z, w0.w, w0.w);
            *reinterpret_cast<float4*>(&Bs2[wr][2*wc +  8]) = make_float4(w1.x, w1.x, w1.y, w1.y);
            *reinterpret_cast<float4*>(&Bs2[wr][2*wc + 12]) = make_float4(w1.z, w1.z, w1.w, w1.w);
        }
        __syncthreads();
        #pragma unroll
        for (int k = 0; k < BK; k++) {
            ulonglong2 av0 = *reinterpret_cast<const ulonglong2*>(&As[k][ty * 8]);
            ulonglong2 av1 = *reinterpret_cast<const ulonglong2*>(&As[k][ty * 8 + 4]);
            const ull ap[4] = {av0.x, av0.y, av1.x, av1.y};
            ulonglong2 bv0 = *reinterpret_cast<const ulonglong2*>(&Bs2[k][tx * 16 +  0]);
            ulonglong2 bv1 = *reinterpret_cast<const ulonglong2*>(&Bs2[k][tx * 16 +  4]);
            ulonglong2 bv2 = *reinterpret_cast<const ulonglong2*>(&Bs2[k][tx * 16 +  8]);
            ulonglong2 bv3 = *reinterpret_cast<const ulonglong2*>(&Bs2[k][tx * 16 + 12]);
            const ull bp[8] = {bv0.x, bv0.y, bv1.x, bv1.y, bv2.x, bv2.y, bv3.x, bv3.y};
            #pragma unroll
            for (int i = 0; i < 4; i++)
                #pragma unroll
                for (int j = 0; j < 8; j++)
                    FFMA2(acc[i][j], ap[i], bp[j]);
        }
        __syncthreads();
    }

    float bb[8];
    #pragma unroll
    for (int j = 0; j < 8; j++) bb[j] = bias[n0 + tx * 8 + j];

    #pragma unroll
    for (int i = 0; i < 4; i++) {
        #pragma unroll
        for (int h = 0; h < 2; h++) {
            const int row = m0 + ty * 8 + 2 * i + h;
            if (row < M) {
                float o[8];
                #pragma unroll
                for (int j = 0; j < 8; j++) {
                    float2 p = *reinterpret_cast<float2*>(&acc[i][j]);
                    o[j] = (h ? p.y : p.x) + bb[j];
                }
                float* cp = C + row * 256 + n0 + tx * 8;
                if (MODE == 1) {
                    float4 c0 = *reinterpret_cast<const float4*>(cp);
                    float4 c1 = *reinterpret_cast<const float4*>(cp + 4);
                    #pragma unroll
                    for (int j = 0; j < 8; j++) o[j] = o[j] > 0.f ? o[j] : 0.01f * o[j];
                    *reinterpret_cast<float4*>(cp)     = make_float4(c0.x + o[0], c0.y + o[1], c0.z + o[2], c0.w + o[3]);
                    *reinterpret_cast<float4*>(cp + 4) = make_float4(c1.x + o[4], c1.y + o[5], c1.z + o[6], c1.w + o[7]);
                } else {
                    *reinterpret_cast<float4*>(cp)     = make_float4(o[0], o[1], o[2], o[3]);
                    *reinterpret_cast<float4*>(cp + 4) = make_float4(o[4], o[5], o[6], o[7]);
                }
            }
        }
    }
}

// ------------------------- fused relay projections (ak, av, q2) ----------------
__global__ __launch_bounds__(256) void small3_k(
    const float* __restrict__ x,
    const float* __restrict__ WK, const float* __restrict__ bK,
    const float* __restrict__ WV, const float* __restrict__ bV,
    const float* __restrict__ WQ, const float* __restrict__ bQ,
    float* __restrict__ ak, float* __restrict__ av, float* __restrict__ q2)
{
    __shared__ float xr[Hh];
    const int b = blockIdx.x, which = blockIdx.y, t = threadIdx.x;
    const float* W; const float* bias; float* out;
    if (which == 0)      { W = WK; bias = bK; out = ak; }
    else if (which == 1) { W = WV; bias = bV; out = av; }
    else                 { W = WQ; bias = bQ; out = q2; }
    xr[t] = x[b * Hh + t];
    __syncthreads();
    float acc = bias[t];
    #pragma unroll 8
    for (int k = 0; k < Hh; k++) acc += xr[k] * W[k * Hh + t];
    out[b * Hh + t] = acc;
}

// ------------------------- relay WO: [32,256]@[256,256] + leaky ----------------
__global__ __launch_bounds__(256) void small_gemm(
    const float* __restrict__ x, const float* __restrict__ W,
    const float* __restrict__ bias, float* __restrict__ out)
{
    __shared__ float xr[Hh];
    const int b = blockIdx.x, t = threadIdx.x;
    xr[t] = x[b * Hh + t];
    __syncthreads();
    float acc = bias[t];
    #pragma unroll 8
    for (int k = 0; k < Hh; k++) acc += xr[k] * W[k * Hh + t];
    acc = acc > 0.f ? acc : 0.01f * acc;
    out[b * Hh + t] = acc;
}

// ------------------------- msa1 attention (window-3 + relay) -------------------
__global__ __launch_bounds__(256) void attn1_k(
    const float* __restrict__ q, const float* __restrict__ k,
    const float* __restrict__ ak, const float* __restrict__ av,
    float* __restrict__ att)
{
    const int row = blockIdx.x;          // b*512 + l
    const int b = row >> 9, l = row & (Ll - 1);
    const int c = threadIdx.x;           // head*32 + d
    const float qv = q[row * Hh + c];
    const float k0 = ak[b * Hh + c];
    const float v0 = av[b * Hh + c];
    const float km = (l > 0)      ? k[(row - 1) * Hh + c] : 0.f;
    const float kc = k[row * Hh + c];
    const float kp = (l < Ll - 1) ? k[(row + 1) * Hh + c] : 0.f;
    float s0 = qv * k0, s1 = qv * km, s2 = qv * kc, s3 = qv * kp;
    #pragma unroll
    for (int o = 16; o; o >>= 1) {
        s0 += __shfl_xor_sync(0xffffffffu, s0, o);
        s1 += __shfl_xor_sync(0xffffffffu, s1, o);
        s2 += __shfl_xor_sync(0xffffffffu, s2, o);
        s3 += __shfl_xor_sync(0xffffffffu, s3, o);
    }
    const float sc = 0.17677669529663687f;   // 1/sqrt(32)
    s0 *= sc; s1 *= sc; s2 *= sc; s3 *= sc;
    float mx = fmaxf(fmaxf(s0, s1), fmaxf(s2, s3));
    float e0 = expf(s0 - mx), e1 = expf(s1 - mx), e2 = expf(s2 - mx), e3 = expf(s3 - mx);
    const float inv = 1.f / (e0 + e1 + e2 + e3);
    // NOTE: window values come from K (faithful to reference bug)
    att[row * Hh + c] = (e0 * v0 + e1 * km + e2 * kc + e3 * kp) * inv;
}

// ------------------------- msa2 attention (relay over 513 keys) ----------------
__global__ __launch_bounds__(256) void attn2_k(
    const float* __restrict__ q2, const float* __restrict__ k2,
    const float* __restrict__ v2, float* __restrict__ att2)
{
    const int b = blockIdx.x, n = blockIdx.y;
    const int w = threadIdx.x >> 5, d = threadIdx.x & 31;
    const int t = threadIdx.x;
    __shared__ float sc[L1];
    __shared__ float red[8];
    __shared__ float part[8][32];
    const float qv = q2[b * Hh + n * HD + d];
    for (int j = w; j < L1; j += 8) {
        float p = qv * k2[(b * L1 + j) * Hh + n * HD + d];
        #pragma unroll
        for (int o = 16; o; o >>= 1) p += __shfl_xor_sync(0xffffffffu, p, o);
        if (d == 0) sc[j] = p * 0.17677669529663687f;
    }
    __syncthreads();
    float mx = -3.4e38f;
    for (int j = t; j < L1; j += 256) mx = fmaxf(mx, sc[j]);
    #pragma unroll
    for (int o = 16; o; o >>= 1) mx = fmaxf(mx, __shfl_xor_sync(0xffffffffu, mx, o));
    if (d == 0) red[w] = mx;
    __syncthreads();
    float gmx = red[0];
    #pragma unroll
    for (int r = 1; r < 8; r++) gmx = fmaxf(gmx, red[r]);
    __syncthreads();
    float ls = 0.f;
    for (int j = t; j < L1; j += 256) { float e = expf(sc[j] - gmx); sc[j] = e; ls += e; }
    #pragma unroll
    for (int o = 16; o; o >>= 1) ls += __shfl_xor_sync(0xffffffffu, ls, o);
    if (d == 0) red[w] = ls;
    __syncthreads();
    float tot = 0.f;
    #pragma unroll
    for (int r = 0; r < 8; r++) tot += red[r];
    const float inv = 1.f / tot;
    float acc = 0.f;
    for (int j = w; j < L1; j += 8) acc += sc[j] * v2[(b * L1 + j) * Hh + n * HD + d];
    part[w][d] = acc;
    __syncthreads();
    if (w == 0) {
        float s = 0.f;
        #pragma unroll
        for (int r = 0; r < 8; r++) s += part[r][d];
        att2[b * Hh + n * HD + d] = s * inv;
    }
}

// ------------------------- mask: nodes[data==1] = 0 ----------------------------
__global__ __launch_bounds__(256) void mask_k(
    const int* __restrict__ data, float* __restrict__ nodes)
{
    const int idx = blockIdx.x * 256 + threadIdx.x;
    if (idx >= Bb * Ll) return;
    if (data[idx] == 1) {
        float4 z = make_float4(0.f, 0.f, 0.f, 0.f);
        float4* p = reinterpret_cast<float4*>(nodes + idx * Hh);
        #pragma unroll
        for (int i = 0; i < Hh / 4; i++) p[i] = z;
    }
}

// ------------------------- final: rep = 0.5*max_l nodes + 0.5*relay ------------
__global__ __launch_bounds__(256) void final_k(
    const float* __restrict__ nodes, const float* __restrict__ relay,
    float* __restrict__ out)
{
    const int b = blockIdx.x, t = threadIdx.x;
    float m = -3.4e38f;
    for (int l = 0; l < Ll; l++) m = fmaxf(m, nodes[(b * Ll + l) * Hh + t]);
    out[b * Hh + t] = 0.5f * m + 0.5f * relay[b * Hh + t];
}

// ------------------------- launch ----------------------------------------------
extern "C" void kernel_launch(void* const* d_in, const int* in_sizes, int n_in,
                              void* d_out, int out_size)
{
    (void)in_sizes; (void)n_in; (void)out_size;
    const int*   data     = (const int*)  d_in[0];
    const float* emb      = (const float*)d_in[1];
    const float* emb_fc_W = (const float*)d_in[2];
    const float* emb_fc_b = (const float*)d_in[3];
    const float* pos_emb  = (const float*)d_in[4];
    const float* ln_g     = (const float*)d_in[5];
    const float* ln_b     = (const float*)d_in[6];
    const float* r_WQ = (const float*)d_in[7];
    const float* r_bQ = (const float*)d_in[8];
    const float* r_WK = (const float*)d_in[9];
    const float* r_bK = (const float*)d_in[10];
    const float* r_WV = (const float*)d_in[11];
    const float* r_bV = (const float*)d_in[12];
    const float* r_WO = (const float*)d_in[13];
    const float* r_bO = (const float*)d_in[14];
    const float* s_WQ = (const float*)d_in[15];
    const float* s_bQ = (const float*)d_in[16];
    const float* s_WK = (const float*)d_in[17];
    const float* s_bK = (const float*)d_in[18];
    const float* s_WV = (const float*)d_in[19];
    const float* s_bV = (const float*)d_in[20];
    const float* s_WO = (const float*)d_in[21];
    const float* s_bO = (const float*)d_in[22];

    float *x0, *ln, *q, *k, *att, *k2, *v2, *relay, *ak, *av, *q2, *att2;
    cudaGetSymbolAddress((void**)&x0,   g_x0);
    cudaGetSymbolAddress((void**)&ln,   g_ln);
    cudaGetSymbolAddress((void**)&q,    g_q);
    cudaGetSymbolAddress((void**)&k,    g_k);
    cudaGetSymbolAddress((void**)&att,  g_att);
    cudaGetSymbolAddress((void**)&k2,   g_k2);
    cudaGetSymbolAddress((void**)&v2,   g_v2);
    cudaGetSymbolAddress((void**)&relay,g_relay);
    cudaGetSymbolAddress((void**)&ak,   g_ak);
    cudaGetSymbolAddress((void**)&av,   g_av);
    cudaGetSymbolAddress((void**)&q2,   g_q2);
    cudaGetSymbolAddress((void**)&att2, g_att2);

    const int M1 = Bb * Ll;      // 16384
    const int M2 = Bb * L1;      // 16416
    const dim3 gQK(M1 / 128, 4);                 // dual: WQ, WK
    const dim3 gWO(M1 / 128, 2);                 // single W, residual+leaky
    const dim3 gKV((M2 + 127) / 128, 4);         // dual + gather: s_WK, s_WV over y

    embed_k<<<Bb * Ll / 32, 256>>>(data, emb, emb_fc_W, emb_fc_b, pos_emb, x0);
    relay_init_k<<<Bb, 256>>>(x0, relay);

    for (int i = 0; i < NITER; i++) {
        const int wo = i * Hh * Hh;
        const int bo = i * Hh;
        ln_k<<<M1, 256>>>(x0, ln_g + bo, ln_b + bo, ln);
        gemm_f2<0,0,1><<<gQK, 256>>>(ln, nullptr, nullptr,
                                     r_WQ + wo, r_bQ + bo, q,
                                     r_WK + wo, r_bK + bo, k, M1);
        small3_k<<<dim3(Bb, 3), 256>>>(relay,
                                       r_WK + wo, r_bK + bo,
                                       r_WV + wo, r_bV + bo,
                                       s_WQ + wo, s_bQ + bo,
                                       ak, av, q2);
        attn1_k<<<M1, 256>>>(q, k, ak, av, att);
        gemm_f2<1,0,0><<<gWO, 256>>>(att, nullptr, nullptr,
                                     r_WO + wo, r_bO + bo, x0,
                                     nullptr, nullptr, nullptr, M1);
        gemm_f2<0,1,1><<<gKV, 256>>>(nullptr, relay, x0,
                                     s_WK + wo, s_bK + bo, k2,
                                     s_WV + wo, s_bV + bo, v2, M2);
        attn2_k<<<dim3(Bb, NH), 256>>>(q2, k2, v2, att2);
        small_gemm<<<Bb, 256>>>(att2, s_WO + wo, s_bO + bo, relay);
        mask_k<<<(Bb * Ll + 255) / 256, 256>>>(data, x0);
    }
    final_k<<<Bb, 256>>>(x0, relay, (float*)d_out);
}

// round 7
// speedup vs baseline: 2.1947x; 2.1947x over previous
#include <cuda_runtime.h>
#include <math.h>

#define Bb   32
#define Ll   512
#define Hh   256
#define EMB  300
#define NH   8
#define HD   32
#define L1   513
#define NITER 6

typedef unsigned long long ull;

// packed f32x2 FMA: c.lo += a.lo*b.lo ; c.hi += a.hi*b.hi
#define FFMA2(c, a, b) \
    asm("fma.rn.f32x2 %0, %1, %2, %0;" : "+l"(c) : "l"(a), "l"(b))

// ------------------------- scratch (static, no allocs) -------------------------
__device__ float g_x0 [Bb*Ll*Hh];   // nodes
__device__ float g_ln [Bb*Ll*Hh];
__device__ float g_q  [Bb*Ll*Hh];
__device__ float g_k  [Bb*Ll*Hh];
__device__ float g_att[Bb*Ll*Hh];
__device__ float g_k2 [Bb*L1*Hh];
__device__ float g_v2 [Bb*L1*Hh];
__device__ float g_relay[Bb*Hh];
__device__ float g_ak [Bb*Hh];
__device__ float g_av [Bb*Hh];
__device__ float g_q2 [Bb*Hh];
__device__ float g_att2[Bb*Hh];

// ------------------------- embedding: x0 = emb[data]@W + b + pos ---------------
__global__ __launch_bounds__(256) void embed_k(
    const int* __restrict__ data, const float* __restrict__ emb,
    const float* __restrict__ W, const float* __restrict__ bias,
    const float* __restrict__ pos, float* __restrict__ x0)
{
    __shared__ float As[32][EMB];
    __shared__ int   toks[32];
    const int r0 = blockIdx.x * 32;
    const int t  = threadIdx.x;
    if (t < 32) toks[t] = data[r0 + t];
    __syncthreads();
    for (int i = t; i < 32 * EMB; i += 256) {
        int r = i / EMB, e = i - r * EMB;
        As[r][e] = emb[toks[r] * EMB + e];
    }
    __syncthreads();
    float acc[32];
    #pragma unroll
    for (int r = 0; r < 32; r++) acc[r] = 0.f;
    for (int e = 0; e < EMB; e++) {
        float w = W[e * Hh + t];
        #pragma unroll
        for (int r = 0; r < 32; r++) acc[r] += As[r][e] * w;
    }
    const float bs = bias[t];
    #pragma unroll
    for (int r = 0; r < 32; r++) {
        int row = r0 + r;
        int l   = row & (Ll - 1);
        x0[row * Hh + t] = acc[r] + bs + pos[l * Hh + t];
    }
}

// ------------------------- relay init: mean over L -----------------------------
__global__ __launch_bounds__(256) void relay_init_k(
    const float* __restrict__ x0, float* __restrict__ relay)
{
    const int b = blockIdx.x, t = threadIdx.x;
    float s = 0.f;
    for (int l = 0; l < Ll; l++) s += x0[(b * Ll + l) * Hh + t];
    relay[b * Hh + t] = s * (1.f / Ll);
}

// ------------------------- layernorm over H=256 --------------------------------
__global__ __launch_bounds__(256) void ln_k(
    const float* __restrict__ x, const float* __restrict__ g,
    const float* __restrict__ b, float* __restrict__ out)
{
    const int row = blockIdx.x, t = threadIdx.x;
    float v = x[row * Hh + t];
    float s = v;
    #pragma unroll
    for (int o = 16; o; o >>= 1) s += __shfl_xor_sync(0xffffffffu, s, o);
    __shared__ float red1[8], red2[8];
    if ((t & 31) == 0) red1[t >> 5] = s;
    __syncthreads();
    float tot = 0.f;
    #pragma unroll
    for (int w = 0; w < 8; w++) tot += red1[w];
    const float mu = tot * (1.f / Hh);
    float dv = v - mu;
    float s2 = dv * dv;
    #pragma unroll
    for (int o = 16; o; o >>= 1) s2 += __shfl_xor_sync(0xffffffffu, s2, o);
    if ((t & 31) == 0) red2[t >> 5] = s2;
    __syncthreads();
    float vtot = 0.f;
    #pragma unroll
    for (int w = 0; w < 8; w++) vtot += red2[w];
    const float var = vtot * (1.f / Hh);
    out[row * Hh + t] = g[t] * dv * rsqrtf(var + 1e-5f) + b[t];
}

// ------------------------- FFMA2 GEMM (k-pair packed) --------------------------
// C[M,256] = A[M,256] @ W[256,256] + bias
// BM=128 x BN=64 x BK=16, 256 threads, per-thread 8x4 outputs.
// f32x2 packs (k_even, k_odd): acc.lo = even-k partial, acc.hi = odd-k partial.
// As[128][20] row-major (k contiguous). Bs[64][20] = W transposed (k contiguous).
// Strided thread tiles: rows m = ty + 16*i, cols n = tx + 16*j (conflict-free).
// MODE 0: store.  MODE 1: C += leaky_relu(.)
// GATHER : A row l1==0 per batch comes from relay, else nodes (y = [relay;nodes])
// DUAL   : blockIdx.y 0..7 -> ny<4: W0 tile ny ; ny>=4: W1 tile ny-4
#define BK   16
#define ASTR 20
template <int MODE, int GATHER, int DUAL>
__global__ __launch_bounds__(256, 2) void gemm_f2(
    const float* __restrict__ A,
    const float* __restrict__ relay, const float* __restrict__ nodes,
    const float* __restrict__ W0, const float* __restrict__ b0, float* __restrict__ C0,
    const float* __restrict__ W1, const float* __restrict__ b1, float* __restrict__ C1,
    int M)
{
    __shared__ float As[128][ASTR];
    __shared__ float Bs[64][ASTR];

    const int t  = threadIdx.x;
    const int ny = blockIdx.y;
    const float* W;  const float* bias;  float* C;
    if (DUAL && ny >= 4) { W = W1; bias = b1; C = C1; }
    else                 { W = W0; bias = b0; C = C0; }
    const int n0 = (DUAL ? (ny & 3) : ny) * 64;
    const int m0 = blockIdx.x * 128;

    const int tx = t & 15;          // col base: n = n0 + tx + 16*j
    const int ty = t >> 4;          // row base: m = m0 + ty + 16*i
    const int ar = t >> 1;          // A-load row 0..127
    const int ac = (t & 1) * 8;     // A-load col 0 or 8
    const int bn = t & 63;          // B-load n 0..63
    const int bk = (t >> 6) * 4;    // B-load k group 0,4,8,12

    // hoisted A row pointer (gather resolved once)
    const int lrow = m0 + ar;
    const bool rowok = lrow < M;
    const float* Arow;
    if (GATHER) {
        const int b  = lrow / L1;
        const int l1 = lrow - b * L1;
        Arow = (l1 == 0) ? (relay + b * Hh) : (nodes + (b * Ll + l1 - 1) * Hh);
    } else {
        Arow = A + lrow * Hh;
    }

    ull acc[8][4];
    #pragma unroll
    for (int i = 0; i < 8; i++)
        #pragma unroll
        for (int j = 0; j < 4; j++) acc[i][j] = 0ull;

    for (int kt = 0; kt < 256; kt += BK) {
        // A tile: row-major, no transpose
        if (rowok) {
            float4 a0 = *reinterpret_cast<const float4*>(Arow + kt + ac);
            float4 a1 = *reinterpret_cast<const float4*>(Arow + kt + ac + 4);
            *reinterpret_cast<float4*>(&As[ar][ac])     = a0;
            *reinterpret_cast<float4*>(&As[ar][ac + 4]) = a1;
        } else {
            float4 z = make_float4(0.f, 0.f, 0.f, 0.f);
            *reinterpret_cast<float4*>(&As[ar][ac])     = z;
            *reinterpret_cast<float4*>(&As[ar][ac + 4]) = z;
        }
        // B tile: transpose W[k][n] -> Bs[n][k]; 4 coalesced scalar LDG + 1 STS.128
        {
            const float* wp = W + (kt + bk) * 256 + n0 + bn;
            float4 wv;
            wv.x = wp[0];
            wv.y = wp[256];
            wv.z = wp[512];
            wv.w = wp[768];
            *reinterpret_cast<float4*>(&Bs[bn][bk]) = wv;
        }
        __syncthreads();
        #pragma unroll
        for (int kh = 0; kh < 4; kh++) {           // 4 k per step (2 f32x2 pairs)
            ulonglong2 b2[4];
            #pragma unroll
            for (int j = 0; j < 4; j++)
                b2[j] = *reinterpret_cast<const ulonglong2*>(&Bs[tx + 16 * j][4 * kh]);
            #pragma unroll
            for (int i = 0; i < 8; i++) {
                ulonglong2 a2 = *reinterpret_cast<const ulonglong2*>(&As[ty + 16 * i][4 * kh]);
                #pragma unroll
                for (int j = 0; j < 4; j++) {
                    FFMA2(acc[i][j], a2.x, b2[j].x);
                    FFMA2(acc[i][j], a2.y, b2[j].y);
                }
            }
        }
        __syncthreads();
    }

    float bb[4];
    #pragma unroll
    for (int j = 0; j < 4; j++) bb[j] = bias[n0 + tx + 16 * j];

    #pragma unroll
    for (int i = 0; i < 8; i++) {
        const int row = m0 + ty + 16 * i;
        if (row < M) {
            float* cp = C + row * 256 + n0 + tx;
            #pragma unroll
            for (int j = 0; j < 4; j++) {
                float2 p = *reinterpret_cast<float2*>(&acc[i][j]);
                float v = p.x + p.y + bb[j];
                if (MODE == 1) {
                    v = v > 0.f ? v : 0.01f * v;
                    cp[16 * j] = cp[16 * j] + v;
                } else {
                    cp[16 * j] = v;
                }
            }
        }
    }
}

// ------------------------- fused relay projections (ak, av, q2) ----------------
__global__ __launch_bounds__(256) void small3_k(
    const float* __restrict__ x,
    const float* __restrict__ WK, const float* __restrict__ bK,
    const float* __restrict__ WV, const float* __restrict__ bV,
    const float* __restrict__ WQ, const float* __restrict__ bQ,
    float* __restrict__ ak, float* __restrict__ av, float* __restrict__ q2)
{
    __shared__ float xr[Hh];
    const int b = blockIdx.x, which = blockIdx.y, t = threadIdx.x;
    const float* W; const float* bias; float* out;
    if (which == 0)      { W = WK; bias = bK; out = ak; }
    else if (which == 1) { W = WV; bias = bV; out = av; }
    else                 { W = WQ; bias = bQ; out = q2; }
    xr[t] = x[b * Hh + t];
    __syncthreads();
    float acc = bias[t];
    #pragma unroll 8
    for (int k = 0; k < Hh; k++) acc += xr[k] * W[k * Hh + t];
    out[b * Hh + t] = acc;
}

// ------------------------- relay WO: [32,256]@[256,256] + leaky ----------------
__global__ __launch_bounds__(256) void small_gemm(
    const float* __restrict__ x, const float* __restrict__ W,
    const float* __restrict__ bias, float* __restrict__ out)
{
    __shared__ float xr[Hh];
    const int b = blockIdx.x, t = threadIdx.x;
    xr[t] = x[b * Hh + t];
    __syncthreads();
    float acc = bias[t];
    #pragma unroll 8
    for (int k = 0; k < Hh; k++) acc += xr[k] * W[k * Hh + t];
    acc = acc > 0.f ? acc : 0.01f * acc;
    out[b * Hh + t] = acc;
}

// ------------------------- msa1 attention (window-3 + relay) -------------------
__global__ __launch_bounds__(256) void attn1_k(
    const float* __restrict__ q, const float* __restrict__ k,
    const float* __restrict__ ak, const float* __restrict__ av,
    float* __restrict__ att)
{
    const int row = blockIdx.x;          // b*512 + l
    const int b = row >> 9, l = row & (Ll - 1);
    const int c = threadIdx.x;           // head*32 + d
    const float qv = q[row * Hh + c];
    const float k0 = ak[b * Hh + c];
    const float v0 = av[b * Hh + c];
    const float km = (l > 0)      ? k[(row - 1) * Hh + c] : 0.f;
    const float kc = k[row * Hh + c];
    const float kp = (l < Ll - 1) ? k[(row + 1) * Hh + c] : 0.f;
    float s0 = qv * k0, s1 = qv * km, s2 = qv * kc, s3 = qv * kp;
    #pragma unroll
    for (int o = 16; o; o >>= 1) {
        s0 += __shfl_xor_sync(0xffffffffu, s0, o);
        s1 += __shfl_xor_sync(0xffffffffu, s1, o);
        s2 += __shfl_xor_sync(0xffffffffu, s2, o);
        s3 += __shfl_xor_sync(0xffffffffu, s3, o);
    }
    const float sc = 0.17677669529663687f;   // 1/sqrt(32)
    s0 *= sc; s1 *= sc; s2 *= sc; s3 *= sc;
    float mx = fmaxf(fmaxf(s0, s1), fmaxf(s2, s3));
    float e0 = expf(s0 - mx), e1 = expf(s1 - mx), e2 = expf(s2 - mx), e3 = expf(s3 - mx);
    const float inv = 1.f / (e0 + e1 + e2 + e3);
    // NOTE: window values come from K (faithful to reference bug)
    att[row * Hh + c] = (e0 * v0 + e1 * km + e2 * kc + e3 * kp) * inv;
}

// ------------------------- msa2 attention (relay over 513 keys) ----------------
__global__ __launch_bounds__(256) void attn2_k(
    const float* __restrict__ q2, const float* __restrict__ k2,
    const float* __restrict__ v2, float* __restrict__ att2)
{
    const int b = blockIdx.x, n = blockIdx.y;
    const int w = threadIdx.x >> 5, d = threadIdx.x & 31;
    const int t = threadIdx.x;
    __shared__ float sc[L1];
    __shared__ float red[8];
    __shared__ float part[8][32];
    const float qv = q2[b * Hh + n * HD + d];
    for (int j = w; j < L1; j += 8) {
        float p = qv * k2[(b * L1 + j) * Hh + n * HD + d];
        #pragma unroll
        for (int o = 16; o; o >>= 1) p += __shfl_xor_sync(0xffffffffu, p, o);
        if (d == 0) sc[j] = p * 0.17677669529663687f;
    }
    __syncthreads();
    float mx = -3.4e38f;
    for (int j = t; j < L1; j += 256) mx = fmaxf(mx, sc[j]);
    #pragma unroll
    for (int o = 16; o; o >>= 1) mx = fmaxf(mx, __shfl_xor_sync(0xffffffffu, mx, o));
    if (d == 0) red[w] = mx;
    __syncthreads();
    float gmx = red[0];
    #pragma unroll
    for (int r = 1; r < 8; r++) gmx = fmaxf(gmx, red[r]);
    __syncthreads();
    float ls = 0.f;
    for (int j = t; j < L1; j += 256) { float e = expf(sc[j] - gmx); sc[j] = e; ls += e; }
    #pragma unroll
    for (int o = 16; o; o >>= 1) ls += __shfl_xor_sync(0xffffffffu, ls, o);
    if (d == 0) red[w] = ls;
    __syncthreads();
    float tot = 0.f;
    #pragma unroll
    for (int r = 0; r < 8; r++) tot += red[r];
    const float inv = 1.f / tot;
    float acc = 0.f;
    for (int j = w; j < L1; j += 8) acc += sc[j] * v2[(b * L1 + j) * Hh + n * HD + d];
    part[w][d] = acc;
    __syncthreads();
    if (w == 0) {
        float s = 0.f;
        #pragma unroll
        for (int r = 0; r < 8; r++) s += part[r][d];
        att2[b * Hh + n * HD + d] = s * inv;
    }
}

// ------------------------- mask: nodes[data==1] = 0 ----------------------------
__global__ __launch_bounds__(256) void mask_k(
    const int* __restrict__ data, float* __restrict__ nodes)
{
    const int idx = blockIdx.x * 256 + threadIdx.x;
    if (idx >= Bb * Ll) return;
    if (data[idx] == 1) {
        float4 z = make_float4(0.f, 0.f, 0.f, 0.f);
        float4* p = reinterpret_cast<float4*>(nodes + idx * Hh);
        #pragma unroll
        for (int i = 0; i < Hh / 4; i++) p[i] = z;
    }
}

// ------------------------- final: rep = 0.5*max_l nodes + 0.5*relay ------------
__global__ __launch_bounds__(256) void final_k(
    const float* __restrict__ nodes, const float* __restrict__ relay,
    float* __restrict__ out)
{
    const int b = blockIdx.x, t = threadIdx.x;
    float m = -3.4e38f;
    for (int l = 0; l < Ll; l++) m = fmaxf(m, nodes[(b * Ll + l) * Hh + t]);
    out[b * Hh + t] = 0.5f * m + 0.5f * relay[b * Hh + t];
}

// ------------------------- launch ----------------------------------------------
extern "C" void kernel_launch(void* const* d_in, const int* in_sizes, int n_in,
                              void* d_out, int out_size)
{
    (void)in_sizes; (void)n_in; (void)out_size;
    const int*   data     = (const int*)  d_in[0];
    const float* emb      = (const float*)d_in[1];
    const float* emb_fc_W = (const float*)d_in[2];
    const float* emb_fc_b = (const float*)d_in[3];
    const float* pos_emb  = (const float*)d_in[4];
    const float* ln_g     = (const float*)d_in[5];
    const float* ln_b     = (const float*)d_in[6];
    const float* r_WQ = (const float*)d_in[7];
    const float* r_bQ = (const float*)d_in[8];
    const float* r_WK = (const float*)d_in[9];
    const float* r_bK = (const float*)d_in[10];
    const float* r_WV = (const float*)d_in[11];
    const float* r_bV = (const float*)d_in[12];
    const float* r_WO = (const float*)d_in[13];
    const float* r_bO = (const float*)d_in[14];
    const float* s_WQ = (const float*)d_in[15];
    const float* s_bQ = (const float*)d_in[16];
    const float* s_WK = (const float*)d_in[17];
    const float* s_bK = (const float*)d_in[18];
    const float* s_WV = (const float*)d_in[19];
    const float* s_bV = (const float*)d_in[20];
    const float* s_WO = (const float*)d_in[21];
    const float* s_bO = (const float*)d_in[22];

    float *x0, *ln, *q, *k, *att, *k2, *v2, *relay, *ak, *av, *q2, *att2;
    cudaGetSymbolAddress((void**)&x0,   g_x0);
    cudaGetSymbolAddress((void**)&ln,   g_ln);
    cudaGetSymbolAddress((void**)&q,    g_q);
    cudaGetSymbolAddress((void**)&k,    g_k);
    cudaGetSymbolAddress((void**)&att,  g_att);
    cudaGetSymbolAddress((void**)&k2,   g_k2);
    cudaGetSymbolAddress((void**)&v2,   g_v2);
    cudaGetSymbolAddress((void**)&relay,g_relay);
    cudaGetSymbolAddress((void**)&ak,   g_ak);
    cudaGetSymbolAddress((void**)&av,   g_av);
    cudaGetSymbolAddress((void**)&q2,   g_q2);
    cudaGetSymbolAddress((void**)&att2, g_att2);

    const int M1 = Bb * Ll;      // 16384
    const int M2 = Bb * L1;      // 16416
    const dim3 gQK(M1 / 128, 8);                 // dual: WQ, WK (4 n-tiles each)
    const dim3 gWO(M1 / 128, 4);                 // single W, residual+leaky
    const dim3 gKV((M2 + 127) / 128, 8);         // dual + gather: s_WK, s_WV over y

    embed_k<<<Bb * Ll / 32, 256>>>(data, emb, emb_fc_W, emb_fc_b, pos_emb, x0);
    relay_init_k<<<Bb, 256>>>(x0, relay);

    for (int i = 0; i < NITER; i++) {
        const int wo = i * Hh * Hh;
        const int bo = i * Hh;
        ln_k<<<M1, 256>>>(x0, ln_g + bo, ln_b + bo, ln);
        gemm_f2<0,0,1><<<gQK, 256>>>(ln, nullptr, nullptr,
                                     r_WQ + wo, r_bQ + bo, q,
                                     r_WK + wo, r_bK + bo, k, M1);
        small3_k<<<dim3(Bb, 3), 256>>>(relay,
                                       r_WK + wo, r_bK + bo,
                                       r_WV + wo, r_bV + bo,
                                       s_WQ + wo, s_bQ + bo,
                                       ak, av, q2);
        attn1_k<<<M1, 256>>>(q, k, ak, av, att);
        gemm_f2<1,0,0><<<gWO, 256>>>(att, nullptr, nullptr,
                                     r_WO + wo, r_bO + bo, x0,
                                     nullptr, nullptr, nullptr, M1);
        gemm_f2<0,1,1><<<gKV, 256>>>(nullptr, relay, x0,
                                     s_WK + wo, s_bK + bo, k2,
                                     s_WV + wo, s_bV + bo, v2, M2);
        attn2_k<<<dim3(Bb, NH), 256>>>(q2, k2, v2, att2);
        small_gemm<<<Bb, 256>>>(att2, s_WO + wo, s_bO + bo, relay);
        mask_k<<<(Bb * Ll + 255) / 256, 256>>>(data, x0);
    }
    final_k<<<Bb, 256>>>(x0, relay, (float*)d_out);
}

// round 11
// speedup vs baseline: 3.3498x; 1.5263x over previous
#include <cuda_runtime.h>
#include <cuda_bf16.h>
#include <math.h>
#include <stdint.h>

#define Bb   32
#define Ll   512
#define Hh   256
#define EMB  300
#define NH   8
#define HD   32
#define L1   513
#define NITER 6

#define ATILES 129
#define AROWS  (ATILES*128)      // 16512
#define TSTR   80                // smem row stride bytes (32 bf16 + 8 pad)
#define STAGE  (128*TSTR)        // 10240 B per tile
#define GSMEM  (4*STAGE)         // 2 stages x (A+B)

// ------------------------- scratch (static, no allocs) -------------------------
__device__ float g_x0 [Bb*Ll*Hh];
__device__ float g_q  [Bb*Ll*Hh];
__device__ float g_k  [Bb*Ll*Hh];
__device__ float g_k2 [Bb*L1*Hh];
__device__ float g_v2 [Bb*L1*Hh];
__device__ float g_relay[Bb*Hh];
__device__ float g_ak [Bb*Hh];
__device__ float g_av [Bb*Hh];
__device__ float g_q2 [Bb*Hh];
__device__ float g_att2[Bb*Hh];
__device__ __nv_bfloat16 g_Aext[(size_t)AROWS*512];       // [row][ hi(256) | lo(256) ]
__device__ __nv_bfloat16 g_Wext[(size_t)30*256*512];      // per mat: [n][ hi(256) | lo(256) ] (k-minor)

// ------------------------- PTX helpers -----------------------------------------
__device__ __forceinline__ uint32_t smem_u32(const void* p) {
    uint32_t a;
    asm("{ .reg .u64 t; cvta.to.shared.u64 t, %1; cvt.u32.u64 %0, t; }"
        : "=r"(a) : "l"(p));
    return a;
}
#define CPA(dst, src) \
    asm volatile("cp.async.cg.shared.global [%0], [%1], 16;" :: "r"(dst), "l"(src))
#define CP_COMMIT() asm volatile("cp.async.commit_group;" ::: "memory")
#define LDM4(r0, r1, r2, r3, a) \
    asm volatile("ldmatrix.sync.aligned.m8n8.x4.shared.b16 {%0,%1,%2,%3}, [%4];" \
                 : "=r"(r0), "=r"(r1), "=r"(r2), "=r"(r3) : "r"(a))
#define MMA16816(d, a, b0, b1) \
    asm volatile("mma.sync.aligned.m16n8k16.row.col.f32.bf16.bf16.f32 " \
                 "{%0,%1,%2,%3}, {%4,%5,%6,%7}, {%8,%9}, {%0,%1,%2,%3};" \
                 : "+f"((d)[0]), "+f"((d)[1]), "+f"((d)[2]), "+f"((d)[3]) \
                 : "r"((a)[0]), "r"((a)[1]), "r"((a)[2]), "r"((a)[3]), \
                   "r"(b0), "r"(b1))

__device__ __forceinline__ void split_store(
    float v, __nv_bfloat16* hi, __nv_bfloat16* lo)
{
    __nv_bfloat16 h = __float2bfloat16(v);
    *hi = h;
    *lo = __float2bfloat16(v - __bfloat162float(h));
}

// ------------------------- HMMA GEMM -------------------------------------------
// C[M,256] = A[M,256]@W[256,256] + bias via 3-term bf16 split (extended K=768).
// grid (Mtiles, 2); 256 threads = 8 warps (4m x 2n), warp tile 32x64.
// mode 0: store; mode 1: C += leaky_relu(.)
__global__ __launch_bounds__(256, 2) void gemm_hmma(
    const __nv_bfloat16* __restrict__ Aext,
    const __nv_bfloat16* __restrict__ Wext,
    const float* __restrict__ bias, float* __restrict__ C, int M, int mode)
{
    extern __shared__ char smem[];
    const uint32_t sb = smem_u32(smem);
    const int t = threadIdx.x, lane = t & 31, wid = t >> 5;
    const int mw = wid >> 1, nw = wid & 1;
    const int m0 = blockIdx.x * 128, n0 = blockIdx.y * 128;

    const char* Ag = (const char*)(Aext + (size_t)m0 * 512);
    const char* Bg = (const char*)(Wext + (size_t)n0 * 512);

    // global->smem load mapping: 2 rows per thread per tile (16B quarters)
    const int lr = t >> 2;
    const int lq = (t & 3) * 16;

    // ldmatrix per-thread address components (conflict-free with 80B stride)
    // A: lanes 0-15 -> rows (k 0-7 halves), lanes 16-31 -> same rows, k 8-15 half
    const uint32_t aoff = (uint32_t)(mw * 32 + (lane & 15)) * TSTR
                        + (uint32_t)((lane >> 4) & 1) * 16;
    // B: n = (lane&7) + bit4*8 ; k-half = bit3
    const uint32_t boff = (uint32_t)(nw * 64 + (lane & 7) + ((lane >> 4) & 1) * 8) * TSTR
                        + (uint32_t)((lane >> 3) & 1) * 16;

    float acc[2][8][4];
    #pragma unroll
    for (int i = 0; i < 2; i++)
        #pragma unroll
        for (int j = 0; j < 8; j++)
            #pragma unroll
            for (int c = 0; c < 4; c++) acc[i][j][c] = 0.f;

    // chunk ch (0..23): 3-term schedule over extended K
    //   ch 0-7 : A_hi x B_hi   (A chunk ch,    B chunk ch)
    //   ch 8-15: A_lo x B_hi   (A chunk ch,    B chunk ch-8)
    //   ch16-23: A_hi x B_lo   (A chunk ch-16, B chunk ch-8)
    #define ISSUE_LOAD(ch, buf) do {                                              \
        const int aC = ((ch) < 16 ? (ch) : (ch) - 16) * 64;                       \
        const int bC = ((ch) < 8  ? (ch) : (ch) - 8) * 64;                        \
        const uint32_t sa = sb + (buf) * (2 * STAGE);                             \
        const uint32_t sB = sa + STAGE;                                           \
        CPA(sa + lr * TSTR + lq,        Ag + (size_t)lr * 1024 + aC + lq);        \
        CPA(sa + (lr+64) * TSTR + lq,   Ag + (size_t)(lr+64) * 1024 + aC + lq);   \
        CPA(sB + lr * TSTR + lq,        Bg + (size_t)lr * 1024 + bC + lq);        \
        CPA(sB + (lr+64) * TSTR + lq,   Bg + (size_t)(lr+64) * 1024 + bC + lq);   \
        CP_COMMIT();                                                              \
    } while (0)

    ISSUE_LOAD(0, 0);
    for (int ch = 0; ch < 24; ch++) {
        if (ch < 23) {
            ISSUE_LOAD(ch + 1, (ch + 1) & 1);
            asm volatile("cp.async.wait_group 1;" ::: "memory");
        } else {
            asm volatile("cp.async.wait_group 0;" ::: "memory");
        }
        __syncthreads();
        const uint32_t sa = sb + (ch & 1) * (2 * STAGE);
        const uint32_t sB = sa + STAGE;
        #pragma unroll
        for (int k16 = 0; k16 < 2; k16++) {
            uint32_t af[2][4], bf[4][4];
            LDM4(af[0][0], af[0][1], af[0][2], af[0][3], sa + aoff + k16 * 32);
            LDM4(af[1][0], af[1][1], af[1][2], af[1][3], sa + aoff + 16 * TSTR + k16 * 32);
            #pragma unroll
            for (int g = 0; g < 4; g++)
                LDM4(bf[g][0], bf[g][1], bf[g][2], bf[g][3],
                     sB + boff + g * 16 * TSTR + k16 * 32);
            #pragma unroll
            for (int mi = 0; mi < 2; mi++)
                #pragma unroll
                for (int g = 0; g < 4; g++) {
                    MMA16816(acc[mi][2 * g],     af[mi], bf[g][0], bf[g][1]);
                    MMA16816(acc[mi][2 * g + 1], af[mi], bf[g][2], bf[g][3]);
                }
        }
        __syncthreads();
    }

    // epilogue
    const int tr = lane >> 2, tc = (lane & 3) * 2;
    const float* bp = bias + n0 + nw * 64;
    #pragma unroll
    for (int mi = 0; mi < 2; mi++) {
        #pragma unroll
        for (int h = 0; h < 2; h++) {
            const int row = m0 + mw * 32 + mi * 16 + tr + h * 8;
            if (row < M) {
                float* cp = C + (size_t)row * 256 + n0 + nw * 64;
                #pragma unroll
                for (int ni = 0; ni < 8; ni++) {
                    const int col = ni * 8 + tc;
                    float v0 = acc[mi][ni][h * 2]     + bp[col];
                    float v1 = acc[mi][ni][h * 2 + 1] + bp[col + 1];
                    if (mode) {
                        v0 = v0 > 0.f ? v0 : 0.01f * v0;
                        v1 = v1 > 0.f ? v1 : 0.01f * v1;
                        float2 o = *reinterpret_cast<const float2*>(cp + col);
                        v0 += o.x; v1 += o.y;
                    }
                    *reinterpret_cast<float2*>(cp + col) = make_float2(v0, v1);
                }
            }
        }
    }
}

// ------------------------- weight conversion (30 mats, transposed split) -------
// Wext[mat][n][0..255]=hi(W[k][n]), [n][256..511]=lo
__global__ __launch_bounds__(256) void convW_k(
    const float* __restrict__ W0, const float* __restrict__ W1,
    const float* __restrict__ W2, const float* __restrict__ W3,
    const float* __restrict__ W4, __nv_bfloat16* __restrict__ Wext)
{
    const int mat = blockIdx.x, ng = blockIdx.y, t = threadIdx.x;
    const int it = mat / 5, which = mat % 5;
    const float* W;
    switch (which) {
        case 0: W = W0; break; case 1: W = W1; break; case 2: W = W2; break;
        case 3: W = W3; break; default: W = W4; break;
    }
    W += (size_t)it * Hh * Hh;
    __shared__ float tile[32][33];
    const int n0 = ng * 32;
    for (int kt = 0; kt < 8; kt++) {
        const int k0 = kt * 32;
        __syncthreads();
        #pragma unroll
        for (int p = 0; p < 4; p++) {
            const int kk = (t >> 5) + p * 8, nn = t & 31;
            tile[kk][nn] = W[(k0 + kk) * 256 + n0 + nn];
        }
        __syncthreads();
        #pragma unroll
        for (int p = 0; p < 4; p++) {
            const int nn = (t >> 5) + p * 8, kk = t & 31;
            const float v = tile[kk][nn];
            const size_t base = ((size_t)mat * 256 + n0 + nn) * 512 + k0 + kk;
            __nv_bfloat16 h = __float2bfloat16(v);
            Wext[base]       = h;
            Wext[base + 256] = __float2bfloat16(v - __bfloat162float(h));
        }
    }
}

// ------------------------- embedding -------------------------------------------
__global__ __launch_bounds__(256) void embed_k(
    const int* __restrict__ data, const float* __restrict__ emb,
    const float* __restrict__ W, const float* __restrict__ bias,
    const float* __restrict__ pos, float* __restrict__ x0)
{
    __shared__ float As[32][EMB];
    __shared__ int   toks[32];
    const int r0 = blockIdx.x * 32;
    const int t  = threadIdx.x;
    if (t < 32) toks[t] = data[r0 + t];
    __syncthreads();
    for (int i = t; i < 32 * EMB; i += 256) {
        int r = i / EMB, e = i - r * EMB;
        As[r][e] = emb[toks[r] * EMB + e];
    }
    __syncthreads();
    float acc[32];
    #pragma unroll
    for (int r = 0; r < 32; r++) acc[r] = 0.f;
    for (int e = 0; e < EMB; e++) {
        float w = W[e * Hh + t];
        #pragma unroll
        for (int r = 0; r < 32; r++) acc[r] += As[r][e] * w;
    }
    const float bs = bias[t];
    #pragma unroll
    for (int r = 0; r < 32; r++) {
        int row = r0 + r;
        int l   = row & (Ll - 1);
        x0[row * Hh + t] = acc[r] + bs + pos[l * Hh + t];
    }
}

// ------------------------- relay init ------------------------------------------
__global__ __launch_bounds__(256) void relay_init_k(
    const float* __restrict__ x0, float* __restrict__ relay)
{
    const int b = blockIdx.x, t = threadIdx.x;
    float s = 0.f;
    for (int l = 0; l < Ll; l++) s += x0[(b * Ll + l) * Hh + t];
    relay[b * Hh + t] = s * (1.f / Ll);
}

// ------------------------- layernorm -> Aext split -----------------------------
__global__ __launch_bounds__(256) void ln_bf16_k(
    const float* __restrict__ x, const float* __restrict__ g,
    const float* __restrict__ b, __nv_bfloat16* __restrict__ Aext)
{
    const int row = blockIdx.x, t = threadIdx.x;
    float v = x[row * Hh + t];
    float s = v;
    #pragma unroll
    for (int o = 16; o; o >>= 1) s += __shfl_xor_sync(0xffffffffu, s, o);
    __shared__ float red1[8], red2[8];
    if ((t & 31) == 0) red1[t >> 5] = s;
    __syncthreads();
    float tot = 0.f;
    #pragma unroll
    for (int w = 0; w < 8; w++) tot += red1[w];
    const float mu = tot * (1.f / Hh);
    float dv = v - mu;
    float s2 = dv * dv;
    #pragma unroll
    for (int o = 16; o; o >>= 1) s2 += __shfl_xor_sync(0xffffffffu, s2, o);
    if ((t & 31) == 0) red2[t >> 5] = s2;
    __syncthreads();
    float vt = 0.f;
    #pragma unroll
    for (int w = 0; w < 8; w++) vt += red2[w];
    const float ov = g[t] * dv * rsqrtf(vt * (1.f / Hh) + 1e-5f) + b[t];
    split_store(ov, Aext + (size_t)row * 512 + t, Aext + (size_t)row * 512 + 256 + t);
}

// ------------------------- relay projections -----------------------------------
__global__ __launch_bounds__(256) void small3_k(
    const float* __restrict__ x,
    const float* __restrict__ WK, const float* __restrict__ bK,
    const float* __restrict__ WV, const float* __restrict__ bV,
    const float* __restrict__ WQ, const float* __restrict__ bQ,
    float* __restrict__ ak, float* __restrict__ av, float* __restrict__ q2)
{
    __shared__ float xr[Hh];
    const int b = blockIdx.x, which = blockIdx.y, t = threadIdx.x;
    const float* W; const float* bias; float* out;
    if (which == 0)      { W = WK; bias = bK; out = ak; }
    else if (which == 1) { W = WV; bias = bV; out = av; }
    else                 { W = WQ; bias = bQ; out = q2; }
    xr[t] = x[b * Hh + t];
    __syncthreads();
    float acc = bias[t];
    #pragma unroll 8
    for (int k = 0; k < Hh; k++) acc += xr[k] * W[k * Hh + t];
    out[b * Hh + t] = acc;
}

__global__ __launch_bounds__(256) void small_gemm(
    const float* __restrict__ x, const float* __restrict__ W,
    const float* __restrict__ bias, float* __restrict__ out)
{
    __shared__ float xr[Hh];
    const int b = blockIdx.x, t = threadIdx.x;
    xr[t] = x[b * Hh + t];
    __syncthreads();
    float acc = bias[t];
    #pragma unroll 8
    for (int k = 0; k < Hh; k++) acc += xr[k] * W[k * Hh + t];
    acc = acc > 0.f ? acc : 0.01f * acc;
    out[b * Hh + t] = acc;
}

// ------------------------- msa1 attention -> Aext split ------------------------
__global__ __launch_bounds__(256) void attn1_k(
    const float* __restrict__ q, const float* __restrict__ k,
    const float* __restrict__ ak, const float* __restrict__ av,
    __nv_bfloat16* __restrict__ Aext)
{
    const int row = blockIdx.x;          // b*512 + l
    const int b = row >> 9, l = row & (Ll - 1);
    const int c = threadIdx.x;
    const float qv = q[row * Hh + c];
    const float k0 = ak[b * Hh + c];
    const float v0 = av[b * Hh + c];
    const float km = (l > 0)      ? k[(row - 1) * Hh + c] : 0.f;
    const float kc = k[row * Hh + c];
    const float kp = (l < Ll - 1) ? k[(row + 1) * Hh + c] : 0.f;
    float s0 = qv * k0, s1 = qv * km, s2 = qv * kc, s3 = qv * kp;
    #pragma unroll
    for (int o = 16; o; o >>= 1) {
        s0 += __shfl_xor_sync(0xffffffffu, s0, o);
        s1 += __shfl_xor_sync(0xffffffffu, s1, o);
        s2 += __shfl_xor_sync(0xffffffffu, s2, o);
        s3 += __shfl_xor_sync(0xffffffffu, s3, o);
    }
    const float sc = 0.17677669529663687f;
    s0 *= sc; s1 *= sc; s2 *= sc; s3 *= sc;
    float mx = fmaxf(fmaxf(s0, s1), fmaxf(s2, s3));
    float e0 = expf(s0 - mx), e1 = expf(s1 - mx), e2 = expf(s2 - mx), e3 = expf(s3 - mx);
    const float inv = 1.f / (e0 + e1 + e2 + e3);
    // NOTE: window values come from K (faithful to reference bug)
    const float o = (e0 * v0 + e1 * km + e2 * kc + e3 * kp) * inv;
    split_store(o, Aext + (size_t)row * 512 + c, Aext + (size_t)row * 512 + 256 + c);
}

// ------------------------- y = [relay; nodes] -> Aext split --------------------
__global__ __launch_bounds__(256) void conv_y_k(
    const float* __restrict__ relay, const float* __restrict__ nodes,
    __nv_bfloat16* __restrict__ Aext)
{
    const int r = blockIdx.x;            // 0..16511 (zero-pad >= 16416)
    const int t = threadIdx.x;
    float v = 0.f;
    if (r < Bb * L1) {
        const int b = r / L1, l1 = r - b * L1;
        v = (l1 == 0) ? relay[b * Hh + t] : nodes[(b * Ll + l1 - 1) * Hh + t];
    }
    split_store(v, Aext + (size_t)r * 512 + t, Aext + (size_t)r * 512 + 256 + t);
}

// ------------------------- msa2 attention --------------------------------------
__global__ __launch_bounds__(256) void attn2_k(
    const float* __restrict__ q2, const float* __restrict__ k2,
    const float* __restrict__ v2, float* __restrict__ att2)
{
    const int b = blockIdx.x, n = blockIdx.y;
    const int w = threadIdx.x >> 5, d = threadIdx.x & 31;
    const int t = threadIdx.x;
    __shared__ float sc[L1];
    __shared__ float red[8];
    __shared__ float part[8][32];
    const float qv = q2[b * Hh + n * HD + d];
    for (int j = w; j < L1; j += 8) {
        float p = qv * k2[(b * L1 + j) * Hh + n * HD + d];
        #pragma unroll
        for (int o = 16; o; o >>= 1) p += __shfl_xor_sync(0xffffffffu, p, o);
        if (d == 0) sc[j] = p * 0.17677669529663687f;
    }
    __syncthreads();
    float mx = -3.4e38f;
    for (int j = t; j < L1; j += 256) mx = fmaxf(mx, sc[j]);
    #pragma unroll
    for (int o = 16; o; o >>= 1) mx = fmaxf(mx, __shfl_xor_sync(0xffffffffu, mx, o));
    if (d == 0) red[w] = mx;
    __syncthreads();
    float gmx = red[0];
    #pragma unroll
    for (int r = 1; r < 8; r++) gmx = fmaxf(gmx, red[r]);
    __syncthreads();
    float ls = 0.f;
    for (int j = t; j < L1; j += 256) { float e = expf(sc[j] - gmx); sc[j] = e; ls += e; }
    #pragma unroll
    for (int o = 16; o; o >>= 1) ls += __shfl_xor_sync(0xffffffffu, ls, o);
    if (d == 0) red[w] = ls;
    __syncthreads();
    float tot = 0.f;
    #pragma unroll
    for (int r = 0; r < 8; r++) tot += red[r];
    const float inv = 1.f / tot;
    float acc = 0.f;
    for (int j = w; j < L1; j += 8) acc += sc[j] * v2[(b * L1 + j) * Hh + n * HD + d];
    part[w][d] = acc;
    __syncthreads();
    if (w == 0) {
        float s = 0.f;
        #pragma unroll
        for (int r = 0; r < 8; r++) s += part[r][d];
        att2[b * Hh + n * HD + d] = s * inv;
    }
}

// ------------------------- mask ------------------------------------------------
__global__ __launch_bounds__(256) void mask_k(
    const int* __restrict__ data, float* __restrict__ nodes)
{
    const int idx = blockIdx.x * 256 + threadIdx.x;
    if (idx >= Bb * Ll) return;
    if (data[idx] == 1) {
        float4 z = make_float4(0.f, 0.f, 0.f, 0.f);
        float4* p = reinterpret_cast<float4*>(nodes + idx * Hh);
        #pragma unroll
        for (int i = 0; i < Hh / 4; i++) p[i] = z;
    }
}

// ------------------------- final -----------------------------------------------
__global__ __launch_bounds__(256) void final_k(
    const float* __restrict__ nodes, const float* __restrict__ relay,
    float* __restrict__ out)
{
    const int b = blockIdx.x, t = threadIdx.x;
    float m = -3.4e38f;
    for (int l = 0; l < Ll; l++) m = fmaxf(m, nodes[(b * Ll + l) * Hh + t]);
    out[b * Hh + t] = 0.5f * m + 0.5f * relay[b * Hh + t];
}

// ------------------------- launch ----------------------------------------------
extern "C" void kernel_launch(void* const* d_in, const int* in_sizes, int n_in,
                              void* d_out, int out_size)
{
    (void)in_sizes; (void)n_in; (void)out_size;
    const int*   data     = (const int*)  d_in[0];
    const float* emb      = (const float*)d_in[1];
    const float* emb_fc_W = (const float*)d_in[2];
    const float* emb_fc_b = (const float*)d_in[3];
    const float* pos_emb  = (const float*)d_in[4];
    const float* ln_g     = (const float*)d_in[5];
    const float* ln_b     = (const float*)d_in[6];
    const float* r_WQ = (const float*)d_in[7];
    const float* r_bQ = (const float*)d_in[8];
    const float* r_WK = (const float*)d_in[9];
    const float* r_bK = (const float*)d_in[10];
    const float* r_WV = (const float*)d_in[11];
    const float* r_bV = (const float*)d_in[12];
    const float* r_WO = (const float*)d_in[13];
    const float* r_bO = (const float*)d_in[14];
    const float* s_WQ = (const float*)d_in[15];
    const float* s_bQ = (const float*)d_in[16];
    const float* s_WK = (const float*)d_in[17];
    const float* s_bK = (const float*)d_in[18];
    const float* s_WV = (const float*)d_in[19];
    const float* s_bV = (const float*)d_in[20];
    const float* s_WO = (const float*)d_in[21];
    const float* s_bO = (const float*)d_in[22];

    float *x0, *q, *k, *k2, *v2, *relay, *ak, *av, *q2, *att2;
    __nv_bfloat16 *Aext, *Wext;
    cudaGetSymbolAddress((void**)&x0,   g_x0);
    cudaGetSymbolAddress((void**)&q,    g_q);
    cudaGetSymbolAddress((void**)&k,    g_k);
    cudaGetSymbolAddress((void**)&k2,   g_k2);
    cudaGetSymbolAddress((void**)&v2,   g_v2);
    cudaGetSymbolAddress((void**)&relay,g_relay);
    cudaGetSymbolAddress((void**)&ak,   g_ak);
    cudaGetSymbolAddress((void**)&av,   g_av);
    cudaGetSymbolAddress((void**)&q2,   g_q2);
    cudaGetSymbolAddress((void**)&att2, g_att2);
    cudaGetSymbolAddress((void**)&Aext, g_Aext);
    cudaGetSymbolAddress((void**)&Wext, g_Wext);

    cudaFuncSetAttribute(gemm_hmma, cudaFuncAttributeMaxDynamicSharedMemorySize, GSMEM);

    const int M1 = Bb * Ll;      // 16384
    const int M2 = Bb * L1;      // 16416
    const size_t WMAT = (size_t)256 * 512;

    embed_k<<<Bb * Ll / 32, 256>>>(data, emb, emb_fc_W, emb_fc_b, pos_emb, x0);
    relay_init_k<<<Bb, 256>>>(x0, relay);
    // mat = it*5 + {0:r_WQ, 1:r_WK, 2:r_WO, 3:s_WK, 4:s_WV}
    convW_k<<<dim3(30, 8), 256>>>(r_WQ, r_WK, r_WO, s_WK, s_WV, Wext);

    for (int i = 0; i < NITER; i++) {
        const int bo = i * Hh;
        const __nv_bfloat16* wQ = Wext + (size_t)(i * 5 + 0) * WMAT;
        const __nv_bfloat16* wK = Wext + (size_t)(i * 5 + 1) * WMAT;
        const __nv_bfloat16* wO = Wext + (size_t)(i * 5 + 2) * WMAT;
        const __nv_bfloat16* wK2 = Wext + (size_t)(i * 5 + 3) * WMAT;
        const __nv_bfloat16* wV2 = Wext + (size_t)(i * 5 + 4) * WMAT;

        ln_bf16_k<<<M1, 256>>>(x0, ln_g + bo, ln_b + bo, Aext);
        gemm_hmma<<<dim3(128, 2), 256, GSMEM>>>(Aext, wQ, r_bQ + bo, q, M1, 0);
        gemm_hmma<<<dim3(128, 2), 256, GSMEM>>>(Aext, wK, r_bK + bo, k, M1, 0);
        small3_k<<<dim3(Bb, 3), 256>>>(relay,
                                       r_WK + i * Hh * Hh, r_bK + bo,
                                       r_WV + i * Hh * Hh, r_bV + bo,
                                       s_WQ + i * Hh * Hh, s_bQ + bo,
                                       ak, av, q2);
        attn1_k<<<M1, 256>>>(q, k, ak, av, Aext);
        gemm_hmma<<<dim3(128, 2), 256, GSMEM>>>(Aext, wO, r_bO + bo, x0, M1, 1);
        conv_y_k<<<AROWS, 256>>>(relay, x0, Aext);
        gemm_hmma<<<dim3(ATILES, 2), 256, GSMEM>>>(Aext, wK2, s_bK + bo, k2, M2, 0);
        gemm_hmma<<<dim3(ATILES, 2), 256, GSMEM>>>(Aext, wV2, s_bV + bo, v2, M2, 0);
        attn2_k<<<dim3(Bb, NH), 256>>>(q2, k2, v2, att2);
        small_gemm<<<Bb, 256>>>(att2, s_WO + i * Hh * Hh, s_bO + bo, relay);
        mask_k<<<(Bb * Ll + 255) / 256, 256>>>(data, x0);
    }
    final_k<<<Bb, 256>>>(x0, relay, (float*)d_out);
}

// round 12
// speedup vs baseline: 3.6131x; 1.0786x over previous
#include <cuda_runtime.h>
#include <cuda_bf16.h>
#include <math.h>
#include <stdint.h>

#define Bb   32
#define Ll   512
#define Hh   256
#define EMB  300
#define NH   8
#define HD   32
#define L1   513
#define NITER 6

#define ATILES 129
#define AROWS  (ATILES*128)      // 16512
#define TSTR   80                // smem row stride bytes (32 bf16 + 8 pad)
#define STAGE  (128*TSTR)        // 10240 B per tile
#define NSTG   3
#define GSMEM  (NSTG*2*STAGE)    // 61440 B

// ------------------------- scratch (static, no allocs) -------------------------
__device__ float g_x0 [Bb*Ll*Hh];
__device__ float g_q  [Bb*Ll*Hh];
__device__ float g_k  [Bb*Ll*Hh];
__device__ float g_k2 [Bb*L1*Hh];
__device__ float g_v2 [Bb*L1*Hh];
__device__ float g_relay[Bb*Hh];
__device__ float g_ak [Bb*Hh];
__device__ float g_av [Bb*Hh];
__device__ float g_q2 [Bb*Hh];
__device__ float g_att2[Bb*Hh];
__device__ __nv_bfloat16 g_Aext[(size_t)AROWS*512];       // [row][ hi(256) | lo(256) ]
__device__ __nv_bfloat16 g_Wext[(size_t)30*256*512];      // per mat: [n][ hi | lo ] (k-minor)

// ------------------------- PTX helpers -----------------------------------------
__device__ __forceinline__ uint32_t smem_u32(const void* p) {
    uint32_t a;
    asm("{ .reg .u64 t; cvta.to.shared.u64 t, %1; cvt.u32.u64 %0, t; }"
        : "=r"(a) : "l"(p));
    return a;
}
#define CPA(dst, src) \
    asm volatile("cp.async.cg.shared.global [%0], [%1], 16;" :: "r"(dst), "l"(src))
#define CP_COMMIT() asm volatile("cp.async.commit_group;" ::: "memory")
#define LDM4(r0, r1, r2, r3, a) \
    asm volatile("ldmatrix.sync.aligned.m8n8.x4.shared.b16 {%0,%1,%2,%3}, [%4];" \
                 : "=r"(r0), "=r"(r1), "=r"(r2), "=r"(r3) : "r"(a))
#define MMA16816(d, a, b0, b1) \
    asm volatile("mma.sync.aligned.m16n8k16.row.col.f32.bf16.bf16.f32 " \
                 "{%0,%1,%2,%3}, {%4,%5,%6,%7}, {%8,%9}, {%0,%1,%2,%3};" \
                 : "+f"((d)[0]), "+f"((d)[1]), "+f"((d)[2]), "+f"((d)[3]) \
                 : "r"((a)[0]), "r"((a)[1]), "r"((a)[2]), "r"((a)[3]), \
                   "r"(b0), "r"(b1))

__device__ __forceinline__ void split_store(
    float v, __nv_bfloat16* hi, __nv_bfloat16* lo)
{
    __nv_bfloat16 h = __float2bfloat16(v);
    *hi = h;
    *lo = __float2bfloat16(v - __bfloat162float(h));
}

// pack 8 floats -> 8 hi bf16 (uint4) + 8 lo bf16 (uint4)
__device__ __forceinline__ void split_pack8(
    const float* v, uint4& hi, uint4& lo)
{
    uint32_t h[4], l[4];
    #pragma unroll
    for (int p = 0; p < 4; p++) {
        __nv_bfloat16 h0 = __float2bfloat16(v[2*p]);
        __nv_bfloat16 h1 = __float2bfloat16(v[2*p+1]);
        __nv_bfloat16 l0 = __float2bfloat16(v[2*p]   - __bfloat162float(h0));
        __nv_bfloat16 l1 = __float2bfloat16(v[2*p+1] - __bfloat162float(h1));
        h[p] = (uint32_t)__bfloat16_as_ushort(h0) | ((uint32_t)__bfloat16_as_ushort(h1) << 16);
        l[p] = (uint32_t)__bfloat16_as_ushort(l0) | ((uint32_t)__bfloat16_as_ushort(l1) << 16);
    }
    hi = make_uint4(h[0], h[1], h[2], h[3]);
    lo = make_uint4(l[0], l[1], l[2], l[3]);
}

// ------------------------- HMMA GEMM -------------------------------------------
// C[M,256] = A[M,256]@W[256,256] + bias via 3-term bf16 split (extended K=768).
// 256 threads = 8 warps (4m x 2n), warp tile 32x64, 3-stage cp.async pipeline.
// MODE 0: store; MODE 1: C += leaky_relu(.)
// DUAL 1: grid.y 0..3 -> {W0 n0, W0 n1, W1 n0, W1 n1}
template <int MODE, int DUAL>
__global__ __launch_bounds__(256, 2) void gemm_hmma(
    const __nv_bfloat16* __restrict__ Aext,
    const __nv_bfloat16* __restrict__ W0, const float* __restrict__ b0,
    float* __restrict__ C0,
    const __nv_bfloat16* __restrict__ W1, const float* __restrict__ b1,
    float* __restrict__ C1, int M)
{
    extern __shared__ char smem[];
    const uint32_t sb = smem_u32(smem);
    const int t = threadIdx.x, lane = t & 31, wid = t >> 5;
    const int mw = wid >> 1, nw = wid & 1;
    const int ny = blockIdx.y;
    const __nv_bfloat16* W;  const float* bias;  float* C;
    if (DUAL && ny >= 2) { W = W1; bias = b1; C = C1; }
    else                 { W = W0; bias = b0; C = C0; }
    const int n0 = (DUAL ? (ny & 1) : ny) * 128;
    const int m0 = blockIdx.x * 128;

    const char* Ag = (const char*)(Aext + (size_t)m0 * 512);
    const char* Bg = (const char*)(W + (size_t)n0 * 512);

    const int lr = t >> 2;
    const int lq = (t & 3) * 16;

    const uint32_t aoff = (uint32_t)(mw * 32 + (lane & 15)) * TSTR
                        + (uint32_t)((lane >> 4) & 1) * 16;
    const uint32_t boff = (uint32_t)(nw * 64 + (lane & 7) + ((lane >> 4) & 1) * 8) * TSTR
                        + (uint32_t)((lane >> 3) & 1) * 16;

    float acc[2][8][4];
    #pragma unroll
    for (int i = 0; i < 2; i++)
        #pragma unroll
        for (int j = 0; j < 8; j++)
            #pragma unroll
            for (int c = 0; c < 4; c++) acc[i][j][c] = 0.f;

    // 3-term schedule over extended K=768:
    //   ch 0-7 : A_hi x B_hi ; ch 8-15: A_lo x B_hi ; ch16-23: A_hi x B_lo
    #define ISSUE_LOAD(ch, buf) do {                                              \
        const int aC = ((ch) < 16 ? (ch) : (ch) - 16) * 64;                       \
        const int bC = ((ch) < 8  ? (ch) : (ch) - 8) * 64;                        \
        const uint32_t sa = sb + (buf) * (2 * STAGE);                             \
        const uint32_t sB = sa + STAGE;                                           \
        CPA(sa + lr * TSTR + lq,        Ag + (size_t)lr * 1024 + aC + lq);        \
        CPA(sa + (lr+64) * TSTR + lq,   Ag + (size_t)(lr+64) * 1024 + aC + lq);   \
        CPA(sB + lr * TSTR + lq,        Bg + (size_t)lr * 1024 + bC + lq);        \
        CPA(sB + (lr+64) * TSTR + lq,   Bg + (size_t)(lr+64) * 1024 + bC + lq);   \
        CP_COMMIT();                                                              \
    } while (0)

    ISSUE_LOAD(0, 0);
    ISSUE_LOAD(1, 1);
    int buf = 0;
    for (int ch = 0; ch < 24; ch++) {
        if (ch + 2 < 24) {
            ISSUE_LOAD(ch + 2, (ch + 2) % NSTG);
            asm volatile("cp.async.wait_group 2;" ::: "memory");
        } else if (ch + 2 == 24) {
            asm volatile("cp.async.wait_group 1;" ::: "memory");
        } else {
            asm volatile("cp.async.wait_group 0;" ::: "memory");
        }
        __syncthreads();
        const uint32_t sa = sb + buf * (2 * STAGE);
        const uint32_t sB = sa + STAGE;
        #pragma unroll
        for (int k16 = 0; k16 < 2; k16++) {
            uint32_t af[2][4], bf[4][4];
            LDM4(af[0][0], af[0][1], af[0][2], af[0][3], sa + aoff + k16 * 32);
            LDM4(af[1][0], af[1][1], af[1][2], af[1][3], sa + aoff + 16 * TSTR + k16 * 32);
            #pragma unroll
            for (int g = 0; g < 4; g++)
                LDM4(bf[g][0], bf[g][1], bf[g][2], bf[g][3],
                     sB + boff + g * 16 * TSTR + k16 * 32);
            #pragma unroll
            for (int mi = 0; mi < 2; mi++)
                #pragma unroll
                for (int g = 0; g < 4; g++) {
                    MMA16816(acc[mi][2 * g],     af[mi], bf[g][0], bf[g][1]);
                    MMA16816(acc[mi][2 * g + 1], af[mi], bf[g][2], bf[g][3]);
                }
        }
        __syncthreads();
        buf = (buf + 1) % NSTG;
    }

    // epilogue
    const int tr = lane >> 2, tc = (lane & 3) * 2;
    const float* bp = bias + n0 + nw * 64;
    #pragma unroll
    for (int mi = 0; mi < 2; mi++) {
        #pragma unroll
        for (int h = 0; h < 2; h++) {
            const int row = m0 + mw * 32 + mi * 16 + tr + h * 8;
            if (row < M) {
                float* cp = C + (size_t)row * 256 + n0 + nw * 64;
                #pragma unroll
                for (int ni = 0; ni < 8; ni++) {
                    const int col = ni * 8 + tc;
                    float v0 = acc[mi][ni][h * 2]     + bp[col];
                    float v1 = acc[mi][ni][h * 2 + 1] + bp[col + 1];
                    if (MODE) {
                        v0 = v0 > 0.f ? v0 : 0.01f * v0;
                        v1 = v1 > 0.f ? v1 : 0.01f * v1;
                        float2 o = *reinterpret_cast<const float2*>(cp + col);
                        v0 += o.x; v1 += o.y;
                    }
                    *reinterpret_cast<float2*>(cp + col) = make_float2(v0, v1);
                }
            }
        }
    }
}

// ------------------------- weight conversion (30 mats, transposed split) -------
__global__ __launch_bounds__(256) void convW_k(
    const float* __restrict__ W0, const float* __restrict__ W1,
    const float* __restrict__ W2, const float* __restrict__ W3,
    const float* __restrict__ W4, __nv_bfloat16* __restrict__ Wext)
{
    const int mat = blockIdx.x, ng = blockIdx.y, t = threadIdx.x;
    const int it = mat / 5, which = mat % 5;
    const float* W;
    switch (which) {
        case 0: W = W0; break; case 1: W = W1; break; case 2: W = W2; break;
        case 3: W = W3; break; default: W = W4; break;
    }
    W += (size_t)it * Hh * Hh;
    __shared__ float tile[32][33];
    const int n0 = ng * 32;
    for (int kt = 0; kt < 8; kt++) {
        const int k0 = kt * 32;
        __syncthreads();
        #pragma unroll
        for (int p = 0; p < 4; p++) {
            const int kk = (t >> 5) + p * 8, nn = t & 31;
            tile[kk][nn] = W[(k0 + kk) * 256 + n0 + nn];
        }
        __syncthreads();
        #pragma unroll
        for (int p = 0; p < 4; p++) {
            const int nn = (t >> 5) + p * 8, kk = t & 31;
            const float v = tile[kk][nn];
            const size_t base = ((size_t)mat * 256 + n0 + nn) * 512 + k0 + kk;
            __nv_bfloat16 h = __float2bfloat16(v);
            Wext[base]       = h;
            Wext[base + 256] = __float2bfloat16(v - __bfloat162float(h));
        }
    }
}

// ------------------------- embedding -------------------------------------------
__global__ __launch_bounds__(256) void embed_k(
    const int* __restrict__ data, const float* __restrict__ emb,
    const float* __restrict__ W, const float* __restrict__ bias,
    const float* __restrict__ pos, float* __restrict__ x0)
{
    __shared__ float As[32][EMB];
    __shared__ int   toks[32];
    const int r0 = blockIdx.x * 32;
    const int t  = threadIdx.x;
    if (t < 32) toks[t] = data[r0 + t];
    __syncthreads();
    for (int i = t; i < 32 * EMB; i += 256) {
        int r = i / EMB, e = i - r * EMB;
        As[r][e] = emb[toks[r] * EMB + e];
    }
    __syncthreads();
    float acc[32];
    #pragma unroll
    for (int r = 0; r < 32; r++) acc[r] = 0.f;
    for (int e = 0; e < EMB; e++) {
        float w = W[e * Hh + t];
        #pragma unroll
        for (int r = 0; r < 32; r++) acc[r] += As[r][e] * w;
    }
    const float bs = bias[t];
    #pragma unroll
    for (int r = 0; r < 32; r++) {
        int row = r0 + r;
        int l   = row & (Ll - 1);
        x0[row * Hh + t] = acc[r] + bs + pos[l * Hh + t];
    }
}

// ------------------------- relay init ------------------------------------------
__global__ __launch_bounds__(256) void relay_init_k(
    const float* __restrict__ x0, float* __restrict__ relay)
{
    const int b = blockIdx.x, t = threadIdx.x;
    float s = 0.f;
    for (int l = 0; l < Ll; l++) s += x0[(b * Ll + l) * Hh + t];
    relay[b * Hh + t] = s * (1.f / Ll);
}

// ------------------------- layernorm (warp/row) -> Aext split ------------------
__global__ __launch_bounds__(256) void ln8_k(
    const float* __restrict__ x, const float* __restrict__ g,
    const float* __restrict__ b, __nv_bfloat16* __restrict__ Aext)
{
    const int lane = threadIdx.x & 31;
    const int row = blockIdx.x * 8 + (threadIdx.x >> 5);
    const float4* xp = reinterpret_cast<const float4*>(x + (size_t)row * 256);
    float4 a0 = xp[lane * 2], a1 = xp[lane * 2 + 1];
    float v[8] = {a0.x, a0.y, a0.z, a0.w, a1.x, a1.y, a1.z, a1.w};
    float s = 0.f;
    #pragma unroll
    for (int i = 0; i < 8; i++) s += v[i];
    #pragma unroll
    for (int o = 16; o; o >>= 1) s += __shfl_xor_sync(0xffffffffu, s, o);
    const float mu = s * (1.f / 256.f);
    float s2 = 0.f;
    #pragma unroll
    for (int i = 0; i < 8; i++) { v[i] -= mu; s2 += v[i] * v[i]; }
    #pragma unroll
    for (int o = 16; o; o >>= 1) s2 += __shfl_xor_sync(0xffffffffu, s2, o);
    const float rs = rsqrtf(s2 * (1.f / 256.f) + 1e-5f);
    const float4* gp = reinterpret_cast<const float4*>(g);
    const float4* bp = reinterpret_cast<const float4*>(b);
    float4 g0 = gp[lane * 2], g1 = gp[lane * 2 + 1];
    float4 b0 = bp[lane * 2], b1 = bp[lane * 2 + 1];
    const float gg[8] = {g0.x, g0.y, g0.z, g0.w, g1.x, g1.y, g1.z, g1.w};
    const float bb[8] = {b0.x, b0.y, b0.z, b0.w, b1.x, b1.y, b1.z, b1.w};
    #pragma unroll
    for (int i = 0; i < 8; i++) v[i] = gg[i] * v[i] * rs + bb[i];
    uint4 hi, lo;
    split_pack8(v, hi, lo);
    uint4* base = reinterpret_cast<uint4*>(Aext + (size_t)row * 512 + lane * 8);
    base[0]  = hi;
    base[32] = lo;      // +256 elems = +32 uint4
}

// ------------------------- relay projections -----------------------------------
__global__ __launch_bounds__(256) void small3_k(
    const float* __restrict__ x,
    const float* __restrict__ WK, const float* __restrict__ bK,
    const float* __restrict__ WV, const float* __restrict__ bV,
    const float* __restrict__ WQ, const float* __restrict__ bQ,
    float* __restrict__ ak, float* __restrict__ av, float* __restrict__ q2)
{
    __shared__ float xr[Hh];
    const int b = blockIdx.x, which = blockIdx.y, t = threadIdx.x;
    const float* W; const float* bias; float* out;
    if (which == 0)      { W = WK; bias = bK; out = ak; }
    else if (which == 1) { W = WV; bias = bV; out = av; }
    else                 { W = WQ; bias = bQ; out = q2; }
    xr[t] = x[b * Hh + t];
    __syncthreads();
    float acc = bias[t];
    #pragma unroll 8
    for (int k = 0; k < Hh; k++) acc += xr[k] * W[k * Hh + t];
    out[b * Hh + t] = acc;
}

__global__ __launch_bounds__(256) void small_gemm(
    const float* __restrict__ x, const float* __restrict__ W,
    const float* __restrict__ bias, float* __restrict__ out)
{
    __shared__ float xr[Hh];
    const int b = blockIdx.x, t = threadIdx.x;
    xr[t] = x[b * Hh + t];
    __syncthreads();
    float acc = bias[t];
    #pragma unroll 8
    for (int k = 0; k < Hh; k++) acc += xr[k] * W[k * Hh + t];
    acc = acc > 0.f ? acc : 0.01f * acc;
    out[b * Hh + t] = acc;
}

// ------------------------- msa1 attention -> Aext split ------------------------
__global__ __launch_bounds__(256) void attn1_k(
    const float* __restrict__ q, const float* __restrict__ k,
    const float* __restrict__ ak, const float* __restrict__ av,
    __nv_bfloat16* __restrict__ Aext)
{
    const int row = blockIdx.x;          // b*512 + l
    const int b = row >> 9, l = row & (Ll - 1);
    const int c = threadIdx.x;
    const float qv = q[row * Hh + c];
    const float k0 = ak[b * Hh + c];
    const float v0 = av[b * Hh + c];
    const float km = (l > 0)      ? k[(row - 1) * Hh + c] : 0.f;
    const float kc = k[row * Hh + c];
    const float kp = (l < Ll - 1) ? k[(row + 1) * Hh + c] : 0.f;
    float s0 = qv * k0, s1 = qv * km, s2 = qv * kc, s3 = qv * kp;
    #pragma unroll
    for (int o = 16; o; o >>= 1) {
        s0 += __shfl_xor_sync(0xffffffffu, s0, o);
        s1 += __shfl_xor_sync(0xffffffffu, s1, o);
        s2 += __shfl_xor_sync(0xffffffffu, s2, o);
        s3 += __shfl_xor_sync(0xffffffffu, s3, o);
    }
    const float sc = 0.17677669529663687f;
    s0 *= sc; s1 *= sc; s2 *= sc; s3 *= sc;
    float mx = fmaxf(fmaxf(s0, s1), fmaxf(s2, s3));
    float e0 = expf(s0 - mx), e1 = expf(s1 - mx), e2 = expf(s2 - mx), e3 = expf(s3 - mx);
    const float inv = 1.f / (e0 + e1 + e2 + e3);
    // NOTE: window values come from K (faithful to reference bug)
    const float o = (e0 * v0 + e1 * km + e2 * kc + e3 * kp) * inv;
    split_store(o, Aext + (size_t)row * 512 + c, Aext + (size_t)row * 512 + 256 + c);
}

// ------------------------- y = [relay; nodes] (warp/row) -> Aext split ---------
__global__ __launch_bounds__(256) void convy8_k(
    const float* __restrict__ relay, const float* __restrict__ nodes,
    __nv_bfloat16* __restrict__ Aext)
{
    const int lane = threadIdx.x & 31;
    const int r = blockIdx.x * 8 + (threadIdx.x >> 5);    // 0..16511
    float v[8] = {0.f, 0.f, 0.f, 0.f, 0.f, 0.f, 0.f, 0.f};
    if (r < Bb * L1) {
        const int b = r / L1, l1 = r - b * L1;
        const float* src = (l1 == 0) ? (relay + b * Hh)
                                     : (nodes + (size_t)(b * Ll + l1 - 1) * Hh);
        const float4* sp = reinterpret_cast<const float4*>(src);
        float4 a0 = sp[lane * 2], a1 = sp[lane * 2 + 1];
        v[0]=a0.x; v[1]=a0.y; v[2]=a0.z; v[3]=a0.w;
        v[4]=a1.x; v[5]=a1.y; v[6]=a1.z; v[7]=a1.w;
    }
    uint4 hi, lo;
    split_pack8(v, hi, lo);
    uint4* base = reinterpret_cast<uint4*>(Aext + (size_t)r * 512 + lane * 8);
    base[0]  = hi;
    base[32] = lo;
}

// ------------------------- msa2 attention --------------------------------------
__global__ __launch_bounds__(256) void attn2_k(
    const float* __restrict__ q2, const float* __restrict__ k2,
    const float* __restrict__ v2, float* __restrict__ att2)
{
    const int b = blockIdx.x, n = blockIdx.y;
    const int w = threadIdx.x >> 5, d = threadIdx.x & 31;
    const int t = threadIdx.x;
    __shared__ float sc[L1];
    __shared__ float red[8];
    __shared__ float part[8][32];
    const float qv = q2[b * Hh + n * HD + d];
    for (int j = w; j < L1; j += 8) {
        float p = qv * k2[(b * L1 + j) * Hh + n * HD + d];
        #pragma unroll
        for (int o = 16; o; o >>= 1) p += __shfl_xor_sync(0xffffffffu, p, o);
        if (d == 0) sc[j] = p * 0.17677669529663687f;
    }
    __syncthreads();
    float mx = -3.4e38f;
    for (int j = t; j < L1; j += 256) mx = fmaxf(mx, sc[j]);
    #pragma unroll
    for (int o = 16; o; o >>= 1) mx = fmaxf(mx, __shfl_xor_sync(0xffffffffu, mx, o));
    if (d == 0) red[w] = mx;
    __syncthreads();
    float gmx = red[0];
    #pragma unroll
    for (int r = 1; r < 8; r++) gmx = fmaxf(gmx, red[r]);
    __syncthreads();
    float ls = 0.f;
    for (int j = t; j < L1; j += 256) { float e = expf(sc[j] - gmx); sc[j] = e; ls += e; }
    #pragma unroll
    for (int o = 16; o; o >>= 1) ls += __shfl_xor_sync(0xffffffffu, ls, o);
    if (d == 0) red[w] = ls;
    __syncthreads();
    float tot = 0.f;
    #pragma unroll
    for (int r = 0; r < 8; r++) tot += red[r];
    const float inv = 1.f / tot;
    float acc = 0.f;
    for (int j = w; j < L1; j += 8) acc += sc[j] * v2[(b * L1 + j) * Hh + n * HD + d];
    part[w][d] = acc;
    __syncthreads();
    if (w == 0) {
        float s = 0.f;
        #pragma unroll
        for (int r = 0; r < 8; r++) s += part[r][d];
        att2[b * Hh + n * HD + d] = s * inv;
    }
}

// ------------------------- mask ------------------------------------------------
__global__ __launch_bounds__(256) void mask_k(
    const int* __restrict__ data, float* __restrict__ nodes)
{
    const int idx = blockIdx.x * 256 + threadIdx.x;
    if (idx >= Bb * Ll) return;
    if (data[idx] == 1) {
        float4 z = make_float4(0.f, 0.f, 0.f, 0.f);
        float4* p = reinterpret_cast<float4*>(nodes + idx * Hh);
        #pragma unroll
        for (int i = 0; i < Hh / 4; i++) p[i] = z;
    }
}

// ------------------------- final -----------------------------------------------
__global__ __launch_bounds__(256) void final_k(
    const float* __restrict__ nodes, const float* __restrict__ relay,
    float* __restrict__ out)
{
    const int b = blockIdx.x, t = threadIdx.x;
    float m = -3.4e38f;
    for (int l = 0; l < Ll; l++) m = fmaxf(m, nodes[(b * Ll + l) * Hh + t]);
    out[b * Hh + t] = 0.5f * m + 0.5f * relay[b * Hh + t];
}

// ------------------------- launch ----------------------------------------------
extern "C" void kernel_launch(void* const* d_in, const int* in_sizes, int n_in,
                              void* d_out, int out_size)
{
    (void)in_sizes; (void)n_in; (void)out_size;
    const int*   data     = (const int*)  d_in[0];
    const float* emb      = (const float*)d_in[1];
    const float* emb_fc_W = (const float*)d_in[2];
    const float* emb_fc_b = (const float*)d_in[3];
    const float* pos_emb  = (const float*)d_in[4];
    const float* ln_g     = (const float*)d_in[5];
    const float* ln_b     = (const float*)d_in[6];
    const float* r_WQ = (const float*)d_in[7];
    const float* r_bQ = (const float*)d_in[8];
    const float* r_WK = (const float*)d_in[9];
    const float* r_bK = (const float*)d_in[10];
    const float* r_WV = (const float*)d_in[11];
    const float* r_bV = (const float*)d_in[12];
    const float* r_WO = (const float*)d_in[13];
    const float* r_bO = (const float*)d_in[14];
    const float* s_WQ = (const float*)d_in[15];
    const float* s_bQ = (const float*)d_in[16];
    const float* s_WK = (const float*)d_in[17];
    const float* s_bK = (const float*)d_in[18];
    const float* s_WV = (const float*)d_in[19];
    const float* s_bV = (const float*)d_in[20];
    const float* s_WO = (const float*)d_in[21];
    const float* s_bO = (const float*)d_in[22];

    float *x0, *q, *k, *k2, *v2, *relay, *ak, *av, *q2, *att2;
    __nv_bfloat16 *Aext, *Wext;
    cudaGetSymbolAddress((void**)&x0,   g_x0);
    cudaGetSymbolAddress((void**)&q,    g_q);
    cudaGetSymbolAddress((void**)&k,    g_k);
    cudaGetSymbolAddress((void**)&k2,   g_k2);
    cudaGetSymbolAddress((void**)&v2,   g_v2);
    cudaGetSymbolAddress((void**)&relay,g_relay);
    cudaGetSymbolAddress((void**)&ak,   g_ak);
    cudaGetSymbolAddress((void**)&av,   g_av);
    cudaGetSymbolAddress((void**)&q2,   g_q2);
    cudaGetSymbolAddress((void**)&att2, g_att2);
    cudaGetSymbolAddress((void**)&Aext, g_Aext);
    cudaGetSymbolAddress((void**)&Wext, g_Wext);

    cudaFuncSetAttribute(gemm_hmma<0,1>, cudaFuncAttributeMaxDynamicSharedMemorySize, GSMEM);
    cudaFuncSetAttribute(gemm_hmma<1,0>, cudaFuncAttributeMaxDynamicSharedMemorySize, GSMEM);

    const int M1 = Bb * Ll;      // 16384
    const int M2 = Bb * L1;      // 16416
    const size_t WMAT = (size_t)256 * 512;

    embed_k<<<Bb * Ll / 32, 256>>>(data, emb, emb_fc_W, emb_fc_b, pos_emb, x0);
    relay_init_k<<<Bb, 256>>>(x0, relay);
    // mat = it*5 + {0:r_WQ, 1:r_WK, 2:r_WO, 3:s_WK, 4:s_WV}
    convW_k<<<dim3(30, 8), 256>>>(r_WQ, r_WK, r_WO, s_WK, s_WV, Wext);

    for (int i = 0; i < NITER; i++) {
        const int bo = i * Hh;
        const __nv_bfloat16* wQ  = Wext + (size_t)(i * 5 + 0) * WMAT;
        const __nv_bfloat16* wK  = Wext + (size_t)(i * 5 + 1) * WMAT;
        const __nv_bfloat16* wO  = Wext + (size_t)(i * 5 + 2) * WMAT;
        const __nv_bfloat16* wK2 = Wext + (size_t)(i * 5 + 3) * WMAT;
        const __nv_bfloat16* wV2 = Wext + (size_t)(i * 5 + 4) * WMAT;

        ln8_k<<<M1 / 8, 256>>>(x0, ln_g + bo, ln_b + bo, Aext);
        gemm_hmma<0,1><<<dim3(128, 4), 256, GSMEM>>>(Aext, wQ, r_bQ + bo, q,
                                                     wK, r_bK + bo, k, M1);
        small3_k<<<dim3(Bb, 3), 256>>>(relay,
                                       r_WK + i * Hh * Hh, r_bK + bo,
                                       r_WV + i * Hh * Hh, r_bV + bo,
                                       s_WQ + i * Hh * Hh, s_bQ + bo,
                                       ak, av, q2);
        attn1_k<<<M1, 256>>>(q, k, ak, av, Aext);
        gemm_hmma<1,0><<<dim3(128, 2), 256, GSMEM>>>(Aext, wO, r_bO + bo, x0,
                                                     nullptr, nullptr, nullptr, M1);
        convy8_k<<<AROWS / 8, 256>>>(relay, x0, Aext);
        gemm_hmma<0,1><<<dim3(ATILES, 4), 256, GSMEM>>>(Aext, wK2, s_bK + bo, k2,
                                                        wV2, s_bV + bo, v2, M2);
        attn2_k<<<dim3(Bb, NH), 256>>>(q2, k2, v2, att2);
        small_gemm<<<Bb, 256>>>(att2, s_WO + i * Hh * Hh, s_bO + bo, relay);
        mask_k<<<(Bb * Ll + 255) / 256, 256>>>(data, x0);
    }
    final_k<<<Bb, 256>>>(x0, relay, (float*)d_out);
}

// round 14
// speedup vs baseline: 4.0032x; 1.1080x over previous
#include <cuda_runtime.h>
#include <cuda_bf16.h>
#include <math.h>
#include <stdint.h>

#define Bb   32
#define Ll   512
#define Hh   256
#define EMB  300
#define NH   8
#define HD   32
#define L1   513
#define NITER 6

#define ATILES 129
#define AROWS  (ATILES*128)      // 16512
#define TSTR   80                // smem row stride bytes (32 bf16 + 8 pad)
#define STAGE  (128*TSTR)        // 10240 B per tile
#define NSTG   3
#define GSMEM  (NSTG*2*STAGE)    // 61440 B

// ------------------------- scratch (static, no allocs) -------------------------
__device__ float g_x0 [Bb*Ll*Hh];
__device__ float g_q  [Bb*Ll*Hh];
__device__ float g_k  [Bb*Ll*Hh];
__device__ float g_k2 [Bb*L1*Hh];
__device__ float g_v2 [Bb*L1*Hh];
__device__ float g_relay[Bb*Hh];
__device__ float g_ak [Bb*Hh];
__device__ float g_av [Bb*Hh];
__device__ float g_q2 [Bb*Hh];
__device__ float g_att2[Bb*Hh];
__device__ __nv_bfloat16 g_Aext[(size_t)AROWS*512];       // [row][ hi(256) | lo(256) ]
__device__ __nv_bfloat16 g_Wext[(size_t)30*256*512];      // per mat: [n][ hi | lo ] (k-minor)

// ------------------------- PTX helpers -----------------------------------------
__device__ __forceinline__ uint32_t smem_u32(const void* p) {
    uint32_t a;
    asm("{ .reg .u64 t; cvta.to.shared.u64 t, %1; cvt.u32.u64 %0, t; }"
        : "=r"(a) : "l"(p));
    return a;
}
#define CPA(dst, src) \
    asm volatile("cp.async.cg.shared.global [%0], [%1], 16;" :: "r"(dst), "l"(src))
#define CP_COMMIT() asm volatile("cp.async.commit_group;" ::: "memory")
#define LDM4(r0, r1, r2, r3, a) \
    asm volatile("ldmatrix.sync.aligned.m8n8.x4.shared.b16 {%0,%1,%2,%3}, [%4];" \
                 : "=r"(r0), "=r"(r1), "=r"(r2), "=r"(r3) : "r"(a))
#define MMA16816(d, a, b0, b1) \
    asm volatile("mma.sync.aligned.m16n8k16.row.col.f32.bf16.bf16.f32 " \
                 "{%0,%1,%2,%3}, {%4,%5,%6,%7}, {%8,%9}, {%0,%1,%2,%3};" \
                 : "+f"((d)[0]), "+f"((d)[1]), "+f"((d)[2]), "+f"((d)[3]) \
                 : "r"((a)[0]), "r"((a)[1]), "r"((a)[2]), "r"((a)[3]), \
                   "r"(b0), "r"(b1))

// pack 8 floats -> 8 hi bf16 (uint4) + 8 lo bf16 (uint4)
__device__ __forceinline__ void split_pack8(
    const float* v, uint4& hi, uint4& lo)
{
    uint32_t h[4], l[4];
    #pragma unroll
    for (int p = 0; p < 4; p++) {
        __nv_bfloat16 h0 = __float2bfloat16(v[2*p]);
        __nv_bfloat16 h1 = __float2bfloat16(v[2*p+1]);
        __nv_bfloat16 l0 = __float2bfloat16(v[2*p]   - __bfloat162float(h0));
        __nv_bfloat16 l1 = __float2bfloat16(v[2*p+1] - __bfloat162float(h1));
        h[p] = (uint32_t)__bfloat16_as_ushort(h0) | ((uint32_t)__bfloat16_as_ushort(h1) << 16);
        l[p] = (uint32_t)__bfloat16_as_ushort(l0) | ((uint32_t)__bfloat16_as_ushort(l1) << 16);
    }
    hi = make_uint4(h[0], h[1], h[2], h[3]);
    lo = make_uint4(l[0], l[1], l[2], l[3]);
}

__device__ __forceinline__ void ld8(float* v, const float* p, int lane) {
    const float4* fp = reinterpret_cast<const float4*>(p);
    float4 a0 = fp[lane * 2], a1 = fp[lane * 2 + 1];
    v[0]=a0.x; v[1]=a0.y; v[2]=a0.z; v[3]=a0.w;
    v[4]=a1.x; v[5]=a1.y; v[6]=a1.z; v[7]=a1.w;
}

__device__ __forceinline__ void zero8(float* v) {
    #pragma unroll
    for (int i = 0; i < 8; i++) v[i] = 0.f;
}

// ------------------------- HMMA GEMM -------------------------------------------
// C[M,256] = A[M,256]@W[256,256] + bias via 3-term bf16 split (extended K=768).
// 256 threads = 8 warps (4m x 2n), warp tile 32x64, 3-stage cp.async pipeline,
// one __syncthreads per chunk.
// MODE 0: store; MODE 1: C += leaky_relu(.)
// DUAL 1: grid.y 0..3 -> {W0 n0, W0 n1, W1 n0, W1 n1}
template <int MODE, int DUAL>
__global__ __launch_bounds__(256, 2) void gemm_hmma(
    const __nv_bfloat16* __restrict__ Aext,
    const __nv_bfloat16* __restrict__ W0, const float* __restrict__ b0,
    float* __restrict__ C0,
    const __nv_bfloat16* __restrict__ W1, const float* __restrict__ b1,
    float* __restrict__ C1, int M)
{
    extern __shared__ char smem[];
    const uint32_t sb = smem_u32(smem);
    const int t = threadIdx.x, lane = t & 31, wid = t >> 5;
    const int mw = wid >> 1, nw = wid & 1;
    const int ny = blockIdx.y;
    const __nv_bfloat16* W;  const float* bias;  float* C;
    if (DUAL && ny >= 2) { W = W1; bias = b1; C = C1; }
    else                 { W = W0; bias = b0; C = C0; }
    const int n0 = (DUAL ? (ny & 1) : ny) * 128;
    const int m0 = blockIdx.x * 128;

    const char* Ag = (const char*)(Aext + (size_t)m0 * 512);
    const char* Bg = (const char*)(W + (size_t)n0 * 512);

    const int lr = t >> 2;
    const int lq = (t & 3) * 16;

    const uint32_t aoff = (uint32_t)(mw * 32 + (lane & 15)) * TSTR
                        + (uint32_t)((lane >> 4) & 1) * 16;
    const uint32_t boff = (uint32_t)(nw * 64 + (lane & 7) + ((lane >> 4) & 1) * 8) * TSTR
                        + (uint32_t)((lane >> 3) & 1) * 16;

    float acc[2][8][4];
    #pragma unroll
    for (int i = 0; i < 2; i++)
        #pragma unroll
        for (int j = 0; j < 8; j++)
            #pragma unroll
            for (int c = 0; c < 4; c++) acc[i][j][c] = 0.f;

    // 3-term schedule over extended K=768:
    //   ch 0-7 : A_hi x B_hi ; ch 8-15: A_lo x B_hi ; ch16-23: A_hi x B_lo
    #define ISSUE_LOAD(ch, buf) do {                                              \
        const int aC = ((ch) < 16 ? (ch) : (ch) - 16) * 64;                       \
        const int bC = ((ch) < 8  ? (ch) : (ch) - 8) * 64;                        \
        const uint32_t sa = sb + (buf) * (2 * STAGE);                             \
        const uint32_t sB = sa + STAGE;                                           \
        CPA(sa + lr * TSTR + lq,        Ag + (size_t)lr * 1024 + aC + lq);        \
        CPA(sa + (lr+64) * TSTR + lq,   Ag + (size_t)(lr+64) * 1024 + aC + lq);   \
        CPA(sB + lr * TSTR + lq,        Bg + (size_t)lr * 1024 + bC + lq);        \
        CPA(sB + (lr+64) * TSTR + lq,   Bg + (size_t)(lr+64) * 1024 + bC + lq);   \
        CP_COMMIT();                                                              \
    } while (0)

    ISSUE_LOAD(0, 0);
    ISSUE_LOAD(1, 1);
    int buf = 0;
    for (int ch = 0; ch < 24; ch++) {
        // in flight at top: groups ch, ch+1 (ch+2 issued after compute)
        if (ch < 23) {
            asm volatile("cp.async.wait_group 1;" ::: "memory");
        } else {
            asm volatile("cp.async.wait_group 0;" ::: "memory");
        }
        __syncthreads();
        const uint32_t sa = sb + buf * (2 * STAGE);
        const uint32_t sB = sa + STAGE;
        #pragma unroll
        for (int k16 = 0; k16 < 2; k16++) {
            uint32_t af[2][4], bf[4][4];
            LDM4(af[0][0], af[0][1], af[0][2], af[0][3], sa + aoff + k16 * 32);
            LDM4(af[1][0], af[1][1], af[1][2], af[1][3], sa + aoff + 16 * TSTR + k16 * 32);
            #pragma unroll
            for (int g = 0; g < 4; g++)
                LDM4(bf[g][0], bf[g][1], bf[g][2], bf[g][3],
                     sB + boff + g * 16 * TSTR + k16 * 32);
            #pragma unroll
            for (int mi = 0; mi < 2; mi++)
                #pragma unroll
                for (int g = 0; g < 4; g++) {
                    MMA16816(acc[mi][2 * g],     af[mi], bf[g][0], bf[g][1]);
                    MMA16816(acc[mi][2 * g + 1], af[mi], bf[g][2], bf[g][3]);
                }
        }
        if (ch + 2 < 24) ISSUE_LOAD(ch + 2, (ch + 2) % NSTG);
        buf = (buf + 1) % NSTG;
    }

    // epilogue
    const int tr = lane >> 2, tc = (lane & 3) * 2;
    const float* bp = bias + n0 + nw * 64;
    #pragma unroll
    for (int mi = 0; mi < 2; mi++) {
        #pragma unroll
        for (int h = 0; h < 2; h++) {
            const int row = m0 + mw * 32 + mi * 16 + tr + h * 8;
            if (row < M) {
                float* cp = C + (size_t)row * 256 + n0 + nw * 64;
                #pragma unroll
                for (int ni = 0; ni < 8; ni++) {
                    const int col = ni * 8 + tc;
                    float v0 = acc[mi][ni][h * 2]     + bp[col];
                    float v1 = acc[mi][ni][h * 2 + 1] + bp[col + 1];
                    if (MODE) {
                        v0 = v0 > 0.f ? v0 : 0.01f * v0;
                        v1 = v1 > 0.f ? v1 : 0.01f * v1;
                        float2 o = *reinterpret_cast<const float2*>(cp + col);
                        v0 += o.x; v1 += o.y;
                    }
                    *reinterpret_cast<float2*>(cp + col) = make_float2(v0, v1);
                }
            }
        }
    }
}

// ------------------------- weight conversion (30 mats, transposed split) -------
__global__ __launch_bounds__(256) void convW_k(
    const float* __restrict__ W0, const float* __restrict__ W1,
    const float* __restrict__ W2, const float* __restrict__ W3,
    const float* __restrict__ W4, __nv_bfloat16* __restrict__ Wext)
{
    const int mat = blockIdx.x, ng = blockIdx.y, t = threadIdx.x;
    const int it = mat / 5, which = mat % 5;
    const float* W;
    switch (which) {
        case 0: W = W0; break; case 1: W = W1; break; case 2: W = W2; break;
        case 3: W = W3; break; default: W = W4; break;
    }
    W += (size_t)it * Hh * Hh;
    __shared__ float tile[32][33];
    const int n0 = ng * 32;
    for (int kt = 0; kt < 8; kt++) {
        const int k0 = kt * 32;
        __syncthreads();
        #pragma unroll
        for (int p = 0; p < 4; p++) {
            const int kk = (t >> 5) + p * 8, nn = t & 31;
            tile[kk][nn] = W[(k0 + kk) * 256 + n0 + nn];
        }
        __syncthreads();
        #pragma unroll
        for (int p = 0; p < 4; p++) {
            const int nn = (t >> 5) + p * 8, kk = t & 31;
            const float v = tile[kk][nn];
            const size_t base = ((size_t)mat * 256 + n0 + nn) * 512 + k0 + kk;
            __nv_bfloat16 h = __float2bfloat16(v);
            Wext[base]       = h;
            Wext[base + 256] = __float2bfloat16(v - __bfloat162float(h));
        }
    }
}

// ------------------------- embedding -------------------------------------------
__global__ __launch_bounds__(256) void embed_k(
    const int* __restrict__ data, const float* __restrict__ emb,
    const float* __restrict__ W, const float* __restrict__ bias,
    const float* __restrict__ pos, float* __restrict__ x0)
{
    __shared__ float As[32][EMB];
    __shared__ int   toks[32];
    const int r0 = blockIdx.x * 32;
    const int t  = threadIdx.x;
    if (t < 32) toks[t] = data[r0 + t];
    __syncthreads();
    for (int i = t; i < 32 * EMB; i += 256) {
        int r = i / EMB, e = i - r * EMB;
        As[r][e] = emb[toks[r] * EMB + e];
    }
    __syncthreads();
    float acc[32];
    #pragma unroll
    for (int r = 0; r < 32; r++) acc[r] = 0.f;
    for (int e = 0; e < EMB; e++) {
        float w = W[e * Hh + t];
        #pragma unroll
        for (int r = 0; r < 32; r++) acc[r] += As[r][e] * w;
    }
    const float bs = bias[t];
    #pragma unroll
    for (int r = 0; r < 32; r++) {
        int row = r0 + r;
        int l   = row & (Ll - 1);
        x0[row * Hh + t] = acc[r] + bs + pos[l * Hh + t];
    }
}

// ------------------------- relay init ------------------------------------------
__global__ __launch_bounds__(256) void relay_init_k(
    const float* __restrict__ x0, float* __restrict__ relay)
{
    const int b = blockIdx.x, t = threadIdx.x;
    float s = 0.f;
    for (int l = 0; l < Ll; l++) s += x0[(b * Ll + l) * Hh + t];
    relay[b * Hh + t] = s * (1.f / Ll);
}

// ------------------------- layernorm (warp/row) -> Aext split ------------------
__global__ __launch_bounds__(256) void ln8_k(
    const float* __restrict__ x, const float* __restrict__ g,
    const float* __restrict__ b, __nv_bfloat16* __restrict__ Aext)
{
    const int lane = threadIdx.x & 31;
    const int row = blockIdx.x * 8 + (threadIdx.x >> 5);
    float v[8];
    ld8(v, x + (size_t)row * 256, lane);
    float s = 0.f;
    #pragma unroll
    for (int i = 0; i < 8; i++) s += v[i];
    #pragma unroll
    for (int o = 16; o; o >>= 1) s += __shfl_xor_sync(0xffffffffu, s, o);
    const float mu = s * (1.f / 256.f);
    float s2 = 0.f;
    #pragma unroll
    for (int i = 0; i < 8; i++) { v[i] -= mu; s2 += v[i] * v[i]; }
    #pragma unroll
    for (int o = 16; o; o >>= 1) s2 += __shfl_xor_sync(0xffffffffu, s2, o);
    const float rs = rsqrtf(s2 * (1.f / 256.f) + 1e-5f);
    float gg[8], bb[8];
    ld8(gg, g, lane);
    ld8(bb, b, lane);
    #pragma unroll
    for (int i = 0; i < 8; i++) v[i] = gg[i] * v[i] * rs + bb[i];
    uint4 hi, lo;
    split_pack8(v, hi, lo);
    uint4* base = reinterpret_cast<uint4*>(Aext + (size_t)row * 512 + lane * 8);
    base[0]  = hi;
    base[32] = lo;
}

// ------------------------- relay projections -----------------------------------
__global__ __launch_bounds__(256) void small3_k(
    const float* __restrict__ x,
    const float* __restrict__ WK, const float* __restrict__ bK,
    const float* __restrict__ WV, const float* __restrict__ bV,
    const float* __restrict__ WQ, const float* __restrict__ bQ,
    float* __restrict__ ak, float* __restrict__ av, float* __restrict__ q2)
{
    __shared__ float xr[Hh];
    const int b = blockIdx.x, which = blockIdx.y, t = threadIdx.x;
    const float* W; const float* bias; float* out;
    if (which == 0)      { W = WK; bias = bK; out = ak; }
    else if (which == 1) { W = WV; bias = bV; out = av; }
    else                 { W = WQ; bias = bQ; out = q2; }
    xr[t] = x[b * Hh + t];
    __syncthreads();
    float acc = bias[t];
    #pragma unroll 8
    for (int k = 0; k < Hh; k++) acc += xr[k] * W[k * Hh + t];
    out[b * Hh + t] = acc;
}

__global__ __launch_bounds__(256) void small_gemm(
    const float* __restrict__ x, const float* __restrict__ W,
    const float* __restrict__ bias, float* __restrict__ out)
{
    __shared__ float xr[Hh];
    const int b = blockIdx.x, t = threadIdx.x;
    xr[t] = x[b * Hh + t];
    __syncthreads();
    float acc = bias[t];
    #pragma unroll 8
    for (int k = 0; k < Hh; k++) acc += xr[k] * W[k * Hh + t];
    acc = acc > 0.f ? acc : 0.01f * acc;
    out[b * Hh + t] = acc;
}

// ------------------------- msa1 attention (warp/row) -> Aext split -------------
__global__ __launch_bounds__(256) void attn1w_k(
    const float* __restrict__ q, const float* __restrict__ k,
    const float* __restrict__ ak, const float* __restrict__ av,
    __nv_bfloat16* __restrict__ Aext)
{
    const int lane = threadIdx.x & 31;
    const int row = blockIdx.x * 8 + (threadIdx.x >> 5);   // b*512 + l
    const int b = row >> 9, l = row & (Ll - 1);

    float qv[8], kc[8], km[8], kp[8], k0[8], v0[8];
    ld8(qv, q + (size_t)row * 256, lane);
    ld8(kc, k + (size_t)row * 256, lane);
    ld8(k0, ak + (size_t)b * 256, lane);
    ld8(v0, av + (size_t)b * 256, lane);
    if (l > 0) {
        ld8(km, k + (size_t)(row - 1) * 256, lane);
    } else {
        zero8(km);
    }
    if (l < Ll - 1) {
        ld8(kp, k + (size_t)(row + 1) * 256, lane);
    } else {
        zero8(kp);
    }

    // per-lane partial dots (lane's 8 channels are all inside one head)
    float s0 = 0.f, s1 = 0.f, s2 = 0.f, s3 = 0.f;
    #pragma unroll
    for (int i = 0; i < 8; i++) {
        s0 += qv[i] * k0[i];
        s1 += qv[i] * km[i];
        s2 += qv[i] * kc[i];
        s3 += qv[i] * kp[i];
    }
    // reduce over the 4 lanes of this head (xor 1, 2 stays within the quad)
    #pragma unroll
    for (int o = 1; o <= 2; o <<= 1) {
        s0 += __shfl_xor_sync(0xffffffffu, s0, o);
        s1 += __shfl_xor_sync(0xffffffffu, s1, o);
        s2 += __shfl_xor_sync(0xffffffffu, s2, o);
        s3 += __shfl_xor_sync(0xffffffffu, s3, o);
    }
    const float sc = 0.17677669529663687f;   // 1/sqrt(32)
    s0 *= sc; s1 *= sc; s2 *= sc; s3 *= sc;
    float mx = fmaxf(fmaxf(s0, s1), fmaxf(s2, s3));
    float e0 = expf(s0 - mx), e1 = expf(s1 - mx), e2 = expf(s2 - mx), e3 = expf(s3 - mx);
    const float inv = 1.f / (e0 + e1 + e2 + e3);
    // NOTE: window values come from K (faithful to reference bug)
    float ov[8];
    #pragma unroll
    for (int i = 0; i < 8; i++)
        ov[i] = (e0 * v0[i] + e1 * km[i] + e2 * kc[i] + e3 * kp[i]) * inv;
    uint4 hi, lo;
    split_pack8(ov, hi, lo);
    uint4* base = reinterpret_cast<uint4*>(Aext + (size_t)row * 512 + lane * 8);
    base[0]  = hi;
    base[32] = lo;
}

// ------------------------- y = [relay; nodes] (warp/row) -> Aext split ---------
__global__ __launch_bounds__(256) void convy8_k(
    const float* __restrict__ relay, const float* __restrict__ nodes,
    __nv_bfloat16* __restrict__ Aext)
{
    const int lane = threadIdx.x & 31;
    const int r = blockIdx.x * 8 + (threadIdx.x >> 5);    // 0..16511
    float v[8];
    zero8(v);
    if (r < Bb * L1) {
        const int b = r / L1, l1 = r - b * L1;
        const float* src = (l1 == 0) ? (relay + b * Hh)
                                     : (nodes + (size_t)(b * Ll + l1 - 1) * Hh);
        ld8(v, src, lane);
    }
    uint4 hi, lo;
    split_pack8(v, hi, lo);
    uint4* base = reinterpret_cast<uint4*>(Aext + (size_t)r * 512 + lane * 8);
    base[0]  = hi;
    base[32] = lo;
}

// ------------------------- msa2 attention --------------------------------------
__global__ __launch_bounds__(256) void attn2_k(
    const float* __restrict__ q2, const float* __restrict__ k2,
    const float* __restrict__ v2, float* __restrict__ att2)
{
    const int b = blockIdx.x, n = blockIdx.y;
    const int w = threadIdx.x >> 5, d = threadIdx.x & 31;
    const int t = threadIdx.x;
    __shared__ float sc[L1];
    __shared__ float red[8];
    __shared__ float part[8][32];
    const float qv = q2[b * Hh + n * HD + d];
    for (int j = w; j < L1; j += 8) {
        float p = qv * k2[(b * L1 + j) * Hh + n * HD + d];
        #pragma unroll
        for (int o = 16; o; o >>= 1) p += __shfl_xor_sync(0xffffffffu, p, o);
        if (d == 0) sc[j] = p * 0.17677669529663687f;
    }
    __syncthreads();
    float mx = -3.4e38f;
    for (int j = t; j < L1; j += 256) mx = fmaxf(mx, sc[j]);
    #pragma unroll
    for (int o = 16; o; o >>= 1) mx = fmaxf(mx, __shfl_xor_sync(0xffffffffu, mx, o));
    if (d == 0) red[w] = mx;
    __syncthreads();
    float gmx = red[0];
    #pragma unroll
    for (int r = 1; r < 8; r++) gmx = fmaxf(gmx, red[r]);
    __syncthreads();
    float ls = 0.f;
    for (int j = t; j < L1; j += 256) { float e = expf(sc[j] - gmx); sc[j] = e; ls += e; }
    #pragma unroll
    for (int o = 16; o; o >>= 1) ls += __shfl_xor_sync(0xffffffffu, ls, o);
    if (d == 0) red[w] = ls;
    __syncthreads();
    float tot = 0.f;
    #pragma unroll
    for (int r = 0; r < 8; r++) tot += red[r];
    const float inv = 1.f / tot;
    float acc = 0.f;
    for (int j = w; j < L1; j += 8) acc += sc[j] * v2[(b * L1 + j) * Hh + n * HD + d];
    part[w][d] = acc;
    __syncthreads();
    if (w == 0) {
        float s = 0.f;
        #pragma unroll
        for (int r = 0; r < 8; r++) s += part[r][d];
        att2[b * Hh + n * HD + d] = s * inv;
    }
}

// ------------------------- mask ------------------------------------------------
__global__ __launch_bounds__(256) void mask_k(
    const int* __restrict__ data, float* __restrict__ nodes)
{
    const int idx = blockIdx.x * 256 + threadIdx.x;
    if (idx >= Bb * Ll) return;
    if (data[idx] == 1) {
        float4 z = make_float4(0.f, 0.f, 0.f, 0.f);
        float4* p = reinterpret_cast<float4*>(nodes + idx * Hh);
        #pragma unroll
        for (int i = 0; i < Hh / 4; i++) p[i] = z;
    }
}

// ------------------------- final -----------------------------------------------
__global__ __launch_bounds__(256) void final_k(
    const float* __restrict__ nodes, const float* __restrict__ relay,
    float* __restrict__ out)
{
    const int b = blockIdx.x, t = threadIdx.x;
    float m = -3.4e38f;
    for (int l = 0; l < Ll; l++) m = fmaxf(m, nodes[(b * Ll + l) * Hh + t]);
    out[b * Hh + t] = 0.5f * m + 0.5f * relay[b * Hh + t];
}

// ------------------------- launch ----------------------------------------------
extern "C" void kernel_launch(void* const* d_in, const int* in_sizes, int n_in,
                              void* d_out, int out_size)
{
    (void)in_sizes; (void)n_in; (void)out_size;
    const int*   data     = (const int*)  d_in[0];
    const float* emb      = (const float*)d_in[1];
    const float* emb_fc_W = (const float*)d_in[2];
    const float* emb_fc_b = (const float*)d_in[3];
    const float* pos_emb  = (const float*)d_in[4];
    const float* ln_g     = (const float*)d_in[5];
    const float* ln_b     = (const float*)d_in[6];
    const float* r_WQ = (const float*)d_in[7];
    const float* r_bQ = (const float*)d_in[8];
    const float* r_WK = (const float*)d_in[9];
    const float* r_bK = (const float*)d_in[10];
    const float* r_WV = (const float*)d_in[11];
    const float* r_bV = (const float*)d_in[12];
    const float* r_WO = (const float*)d_in[13];
    const float* r_bO = (const float*)d_in[14];
    const float* s_WQ = (const float*)d_in[15];
    const float* s_bQ = (const float*)d_in[16];
    const float* s_WK = (const float*)d_in[17];
    const float* s_bK = (const float*)d_in[18];
    const float* s_WV = (const float*)d_in[19];
    const float* s_bV = (const float*)d_in[20];
    const float* s_WO = (const float*)d_in[21];
    const float* s_bO = (const float*)d_in[22];

    float *x0, *q, *k, *k2, *v2, *relay, *ak, *av, *q2, *att2;
    __nv_bfloat16 *Aext, *Wext;
    cudaGetSymbolAddress((void**)&x0,   g_x0);
    cudaGetSymbolAddress((void**)&q,    g_q);
    cudaGetSymbolAddress((void**)&k,    g_k);
    cudaGetSymbolAddress((void**)&k2,   g_k2);
    cudaGetSymbolAddress((void**)&v2,   g_v2);
    cudaGetSymbolAddress((void**)&relay,g_relay);
    cudaGetSymbolAddress((void**)&ak,   g_ak);
    cudaGetSymbolAddress((void**)&av,   g_av);
    cudaGetSymbolAddress((void**)&q2,   g_q2);
    cudaGetSymbolAddress((void**)&att2, g_att2);
    cudaGetSymbolAddress((void**)&Aext, g_Aext);
    cudaGetSymbolAddress((void**)&Wext, g_Wext);

    cudaFuncSetAttribute(gemm_hmma<0,1>, cudaFuncAttributeMaxDynamicSharedMemorySize, GSMEM);
    cudaFuncSetAttribute(gemm_hmma<1,0>, cudaFuncAttributeMaxDynamicSharedMemorySize, GSMEM);

    const int M1 = Bb * Ll;      // 16384
    const int M2 = Bb * L1;      // 16416
    const size_t WMAT = (size_t)256 * 512;

    embed_k<<<Bb * Ll / 32, 256>>>(data, emb, emb_fc_W, emb_fc_b, pos_emb, x0);   // launch 1
    relay_init_k<<<Bb, 256>>>(x0, relay);                                          // launch 2
    // mat = it*5 + {0:r_WQ, 1:r_WK, 2:r_WO, 3:s_WK, 4:s_WV}
    convW_k<<<dim3(30, 8), 256>>>(r_WQ, r_WK, r_WO, s_WK, s_WV, Wext);             // launch 3

    for (int i = 0; i < NITER; i++) {
        const int bo = i * Hh;
        const __nv_bfloat16* wQ  = Wext + (size_t)(i * 5 + 0) * WMAT;
        const __nv_bfloat16* wK  = Wext + (size_t)(i * 5 + 1) * WMAT;
        const __nv_bfloat16* wO  = Wext + (size_t)(i * 5 + 2) * WMAT;
        const __nv_bfloat16* wK2 = Wext + (size_t)(i * 5 + 3) * WMAT;
        const __nv_bfloat16* wV2 = Wext + (size_t)(i * 5 + 4) * WMAT;

        // small3 before ln8: only depends on relay; aligns gemm_hmma as the 6th
        // global launch so ncu (-s 5 -c 1) captures the GEMM.
        small3_k<<<dim3(Bb, 3), 256>>>(relay,                                      // it0: launch 4
                                       r_WK + i * Hh * Hh, r_bK + bo,
                                       r_WV + i * Hh * Hh, r_bV + bo,
                                       s_WQ + i * Hh * Hh, s_bQ + bo,
                                       ak, av, q2);
        ln8_k<<<M1 / 8, 256>>>(x0, ln_g + bo, ln_b + bo, Aext);                    // it0: launch 5
        gemm_hmma<0,1><<<dim3(128, 4), 256, GSMEM>>>(Aext, wQ, r_bQ + bo, q,       // it0: launch 6
                                                     wK, r_bK + bo, k, M1);
        attn1w_k<<<M1 / 8, 256>>>(q, k, ak, av, Aext);
        gemm_hmma<1,0><<<dim3(128, 2), 256, GSMEM>>>(Aext, wO, r_bO + bo, x0,
                                                     nullptr, nullptr, nullptr, M1);
        convy8_k<<<AROWS / 8, 256>>>(relay, x0, Aext);
        gemm_hmma<0,1><<<dim3(ATILES, 4), 256, GSMEM>>>(Aext, wK2, s_bK + bo, k2,
                                                        wV2, s_bV + bo, v2, M2);
        attn2_k<<<dim3(Bb, NH), 256>>>(q2, k2, v2, att2);
        small_gemm<<<Bb, 256>>>(att2, s_WO + i * Hh * Hh, s_bO + bo, relay);
        mask_k<<<(Bb * Ll + 255) / 256, 256>>>(data, x0);
    }
    final_k<<<Bb, 256>>>(x0, relay, (float*)d_out);
}

// round 15
// speedup vs baseline: 4.5351x; 1.1329x over previous
#include <cuda_runtime.h>
#include <cuda_bf16.h>
#include <math.h>
#include <stdint.h>

#define Bb   32
#define Ll   512
#define Hh   256
#define EMB  300
#define NH   8
#define HD   32
#define L1   513
#define NITER 6

#define ATILES 129
#define AROWS  (ATILES*128)      // 16512
#define TSTR   80                // smem row stride bytes (32 bf16 + 8 pad)
#define STAGE  (128*TSTR)        // 10240 B per tile
#define NSTG   3
#define GSMEM  (NSTG*2*STAGE)    // 61440 B

// ------------------------- scratch (static, no allocs) -------------------------
__device__ float g_x0 [Bb*Ll*Hh];
__device__ float g_q  [Bb*Ll*Hh];
__device__ float g_k  [Bb*Ll*Hh];
__device__ float g_k2 [Bb*L1*Hh];
__device__ float g_v2 [Bb*L1*Hh];
__device__ float g_relay[Bb*Hh];
__device__ float g_ak [Bb*Hh];
__device__ float g_av [Bb*Hh];
__device__ float g_q2 [Bb*Hh];
__device__ float g_att2[Bb*Hh];
__device__ __nv_bfloat16 g_Aext[(size_t)AROWS*512];       // [row][ hi(256) | lo(256) ]
__device__ __nv_bfloat16 g_Wext[(size_t)30*256*512];      // per mat: [n][ hi | lo ] (k-minor)

// ------------------------- PTX helpers -----------------------------------------
__device__ __forceinline__ uint32_t smem_u32(const void* p) {
    uint32_t a;
    asm("{ .reg .u64 t; cvta.to.shared.u64 t, %1; cvt.u32.u64 %0, t; }"
        : "=r"(a) : "l"(p));
    return a;
}
#define CPA(dst, src) \
    asm volatile("cp.async.cg.shared.global [%0], [%1], 16;" :: "r"(dst), "l"(src))
#define CP_COMMIT() asm volatile("cp.async.commit_group;" ::: "memory")
#define LDM4(r0, r1, r2, r3, a) \
    asm volatile("ldmatrix.sync.aligned.m8n8.x4.shared.b16 {%0,%1,%2,%3}, [%4];" \
                 : "=r"(r0), "=r"(r1), "=r"(r2), "=r"(r3) : "r"(a))
#define MMA16816(d, a, b0, b1) \
    asm volatile("mma.sync.aligned.m16n8k16.row.col.f32.bf16.bf16.f32 " \
                 "{%0,%1,%2,%3}, {%4,%5,%6,%7}, {%8,%9}, {%0,%1,%2,%3};" \
                 : "+f"((d)[0]), "+f"((d)[1]), "+f"((d)[2]), "+f"((d)[3]) \
                 : "r"((a)[0]), "r"((a)[1]), "r"((a)[2]), "r"((a)[3]), \
                   "r"(b0), "r"(b1))

// pack 8 floats -> 8 hi bf16 (uint4) + 8 lo bf16 (uint4)
__device__ __forceinline__ void split_pack8(
    const float* v, uint4& hi, uint4& lo)
{
    uint32_t h[4], l[4];
    #pragma unroll
    for (int p = 0; p < 4; p++) {
        __nv_bfloat16 h0 = __float2bfloat16(v[2*p]);
        __nv_bfloat16 h1 = __float2bfloat16(v[2*p+1]);
        __nv_bfloat16 l0 = __float2bfloat16(v[2*p]   - __bfloat162float(h0));
        __nv_bfloat16 l1 = __float2bfloat16(v[2*p+1] - __bfloat162float(h1));
        h[p] = (uint32_t)__bfloat16_as_ushort(h0) | ((uint32_t)__bfloat16_as_ushort(h1) << 16);
        l[p] = (uint32_t)__bfloat16_as_ushort(l0) | ((uint32_t)__bfloat16_as_ushort(l1) << 16);
    }
    hi = make_uint4(h[0], h[1], h[2], h[3]);
    lo = make_uint4(l[0], l[1], l[2], l[3]);
}

__device__ __forceinline__ void ld8(float* v, const float* p, int lane) {
    const float4* fp = reinterpret_cast<const float4*>(p);
    float4 a0 = fp[lane * 2], a1 = fp[lane * 2 + 1];
    v[0]=a0.x; v[1]=a0.y; v[2]=a0.z; v[3]=a0.w;
    v[4]=a1.x; v[5]=a1.y; v[6]=a1.z; v[7]=a1.w;
}

__device__ __forceinline__ void zero8(float* v) {
    #pragma unroll
    for (int i = 0; i < 8; i++) v[i] = 0.f;
}

// ------------------------- HMMA GEMM -------------------------------------------
// C[M,256] = A[M,256]@W[256,256] + bias via 3-term bf16 split (extended K=768).
// 256 threads = 8 warps (4m x 2n), warp tile 32x64, 3-stage cp.async pipeline,
// one __syncthreads per chunk.
// MODE 0: store; MODE 1: C += leaky_relu(.)
// DUAL 1: grid.y 0..3 -> {W0 n0, W0 n1, W1 n0, W1 n1}
template <int MODE, int DUAL>
__global__ __launch_bounds__(256, 2) void gemm_hmma(
    const __nv_bfloat16* __restrict__ Aext,
    const __nv_bfloat16* __restrict__ W0, const float* __restrict__ b0,
    float* __restrict__ C0,
    const __nv_bfloat16* __restrict__ W1, const float* __restrict__ b1,
    float* __restrict__ C1, int M)
{
    extern __shared__ char smem[];
    const uint32_t sb = smem_u32(smem);
    const int t = threadIdx.x, lane = t & 31, wid = t >> 5;
    const int mw = wid >> 1, nw = wid & 1;
    const int ny = blockIdx.y;
    const __nv_bfloat16* W;  const float* bias;  float* C;
    if (DUAL && ny >= 2) { W = W1; bias = b1; C = C1; }
    else                 { W = W0; bias = b0; C = C0; }
    const int n0 = (DUAL ? (ny & 1) : ny) * 128;
    const int m0 = blockIdx.x * 128;

    const char* Ag = (const char*)(Aext + (size_t)m0 * 512);
    const char* Bg = (const char*)(W + (size_t)n0 * 512);

    const int lr = t >> 2;
    const int lq = (t & 3) * 16;

    const uint32_t aoff = (uint32_t)(mw * 32 + (lane & 15)) * TSTR
                        + (uint32_t)((lane >> 4) & 1) * 16;
    const uint32_t boff = (uint32_t)(nw * 64 + (lane & 7) + ((lane >> 4) & 1) * 8) * TSTR
                        + (uint32_t)((lane >> 3) & 1) * 16;

    float acc[2][8][4];
    #pragma unroll
    for (int i = 0; i < 2; i++)
        #pragma unroll
        for (int j = 0; j < 8; j++)
            #pragma unroll
            for (int c = 0; c < 4; c++) acc[i][j][c] = 0.f;

    // 3-term schedule over extended K=768:
    //   ch 0-7 : A_hi x B_hi ; ch 8-15: A_lo x B_hi ; ch16-23: A_hi x B_lo
    #define ISSUE_LOAD(ch, buf) do {                                              \
        const int aC = ((ch) < 16 ? (ch) : (ch) - 16) * 64;                       \
        const int bC = ((ch) < 8  ? (ch) : (ch) - 8) * 64;                        \
        const uint32_t sa = sb + (buf) * (2 * STAGE);                             \
        const uint32_t sB = sa + STAGE;                                           \
        CPA(sa + lr * TSTR + lq,        Ag + (size_t)lr * 1024 + aC + lq);        \
        CPA(sa + (lr+64) * TSTR + lq,   Ag + (size_t)(lr+64) * 1024 + aC + lq);   \
        CPA(sB + lr * TSTR + lq,        Bg + (size_t)lr * 1024 + bC + lq);        \
        CPA(sB + (lr+64) * TSTR + lq,   Bg + (size_t)(lr+64) * 1024 + bC + lq);   \
        CP_COMMIT();                                                              \
    } while (0)

    ISSUE_LOAD(0, 0);
    ISSUE_LOAD(1, 1);
    int buf = 0;
    for (int ch = 0; ch < 24; ch++) {
        if (ch < 23) {
            asm volatile("cp.async.wait_group 1;" ::: "memory");
        } else {
            asm volatile("cp.async.wait_group 0;" ::: "memory");
        }
        __syncthreads();
        const uint32_t sa = sb + buf * (2 * STAGE);
        const uint32_t sB = sa + STAGE;
        #pragma unroll
        for (int k16 = 0; k16 < 2; k16++) {
            uint32_t af[2][4], bf[4][4];
            LDM4(af[0][0], af[0][1], af[0][2], af[0][3], sa + aoff + k16 * 32);
            LDM4(af[1][0], af[1][1], af[1][2], af[1][3], sa + aoff + 16 * TSTR + k16 * 32);
            #pragma unroll
            for (int g = 0; g < 4; g++)
                LDM4(bf[g][0], bf[g][1], bf[g][2], bf[g][3],
                     sB + boff + g * 16 * TSTR + k16 * 32);
            #pragma unroll
            for (int mi = 0; mi < 2; mi++)
                #pragma unroll
                for (int g = 0; g < 4; g++) {
                    MMA16816(acc[mi][2 * g],     af[mi], bf[g][0], bf[g][1]);
                    MMA16816(acc[mi][2 * g + 1], af[mi], bf[g][2], bf[g][3]);
                }
        }
        if (ch + 2 < 24) ISSUE_LOAD(ch + 2, (ch + 2) % NSTG);
        buf = (buf + 1) % NSTG;
    }

    // epilogue
    const int tr = lane >> 2, tc = (lane & 3) * 2;
    const float* bp = bias + n0 + nw * 64;
    #pragma unroll
    for (int mi = 0; mi < 2; mi++) {
        #pragma unroll
        for (int h = 0; h < 2; h++) {
            const int row = m0 + mw * 32 + mi * 16 + tr + h * 8;
            if (row < M) {
                float* cp = C + (size_t)row * 256 + n0 + nw * 64;
                #pragma unroll
                for (int ni = 0; ni < 8; ni++) {
                    const int col = ni * 8 + tc;
                    float v0 = acc[mi][ni][h * 2]     + bp[col];
                    float v1 = acc[mi][ni][h * 2 + 1] + bp[col + 1];
                    if (MODE) {
                        v0 = v0 > 0.f ? v0 : 0.01f * v0;
                        v1 = v1 > 0.f ? v1 : 0.01f * v1;
                        float2 o = *reinterpret_cast<const float2*>(cp + col);
                        v0 += o.x; v1 += o.y;
                    }
                    *reinterpret_cast<float2*>(cp + col) = make_float2(v0, v1);
                }
            }
        }
    }
}

// ------------------------- weight conversion (30 mats, transposed split) -------
__global__ __launch_bounds__(256) void convW_k(
    const float* __restrict__ W0, const float* __restrict__ W1,
    const float* __restrict__ W2, const float* __restrict__ W3,
    const float* __restrict__ W4, __nv_bfloat16* __restrict__ Wext)
{
    const int mat = blockIdx.x, ng = blockIdx.y, t = threadIdx.x;
    const int it = mat / 5, which = mat % 5;
    const float* W;
    switch (which) {
        case 0: W = W0; break; case 1: W = W1; break; case 2: W = W2; break;
        case 3: W = W3; break; default: W = W4; break;
    }
    W += (size_t)it * Hh * Hh;
    __shared__ float tile[32][33];
    const int n0 = ng * 32;
    for (int kt = 0; kt < 8; kt++) {
        const int k0 = kt * 32;
        __syncthreads();
        #pragma unroll
        for (int p = 0; p < 4; p++) {
            const int kk = (t >> 5) + p * 8, nn = t & 31;
            tile[kk][nn] = W[(k0 + kk) * 256 + n0 + nn];
        }
        __syncthreads();
        #pragma unroll
        for (int p = 0; p < 4; p++) {
            const int nn = (t >> 5) + p * 8, kk = t & 31;
            const float v = tile[kk][nn];
            const size_t base = ((size_t)mat * 256 + n0 + nn) * 512 + k0 + kk;
            __nv_bfloat16 h = __float2bfloat16(v);
            Wext[base]       = h;
            Wext[base + 256] = __float2bfloat16(v - __bfloat162float(h));
        }
    }
}

// ------------------------- embedding -------------------------------------------
__global__ __launch_bounds__(256) void embed_k(
    const int* __restrict__ data, const float* __restrict__ emb,
    const float* __restrict__ W, const float* __restrict__ bias,
    const float* __restrict__ pos, float* __restrict__ x0)
{
    __shared__ float As[32][EMB];
    __shared__ int   toks[32];
    const int r0 = blockIdx.x * 32;
    const int t  = threadIdx.x;
    if (t < 32) toks[t] = data[r0 + t];
    __syncthreads();
    for (int i = t; i < 32 * EMB; i += 256) {
        int r = i / EMB, e = i - r * EMB;
        As[r][e] = emb[toks[r] * EMB + e];
    }
    __syncthreads();
    float acc[32];
    #pragma unroll
    for (int r = 0; r < 32; r++) acc[r] = 0.f;
    for (int e = 0; e < EMB; e++) {
        float w = W[e * Hh + t];
        #pragma unroll
        for (int r = 0; r < 32; r++) acc[r] += As[r][e] * w;
    }
    const float bs = bias[t];
    #pragma unroll
    for (int r = 0; r < 32; r++) {
        int row = r0 + r;
        int l   = row & (Ll - 1);
        x0[row * Hh + t] = acc[r] + bs + pos[l * Hh + t];
    }
}

// ------------------------- relay init (1024 thr, l-split) ----------------------
__global__ __launch_bounds__(1024) void relay_init_k(
    const float* __restrict__ x0, float* __restrict__ relay)
{
    __shared__ float part[3][Hh];
    const int b = blockIdx.x;
    const int col = threadIdx.x & 255, lq = threadIdx.x >> 8;   // 4 slices of 128
    float s = 0.f;
    #pragma unroll 16
    for (int l = lq * 128; l < lq * 128 + 128; l++)
        s += x0[((size_t)b * Ll + l) * Hh + col];
    if (lq > 0) part[lq - 1][col] = s;
    __syncthreads();
    if (lq == 0)
        relay[b * Hh + col] = (s + part[0][col] + part[1][col] + part[2][col]) * (1.f / Ll);
}

// ------------------------- layernorm (warp/row) -> Aext split ------------------
__global__ __launch_bounds__(256) void ln8_k(
    const float* __restrict__ x, const float* __restrict__ g,
    const float* __restrict__ b, __nv_bfloat16* __restrict__ Aext)
{
    const int lane = threadIdx.x & 31;
    const int row = blockIdx.x * 8 + (threadIdx.x >> 5);
    float v[8];
    ld8(v, x + (size_t)row * 256, lane);
    float s = 0.f;
    #pragma unroll
    for (int i = 0; i < 8; i++) s += v[i];
    #pragma unroll
    for (int o = 16; o; o >>= 1) s += __shfl_xor_sync(0xffffffffu, s, o);
    const float mu = s * (1.f / 256.f);
    float s2 = 0.f;
    #pragma unroll
    for (int i = 0; i < 8; i++) { v[i] -= mu; s2 += v[i] * v[i]; }
    #pragma unroll
    for (int o = 16; o; o >>= 1) s2 += __shfl_xor_sync(0xffffffffu, s2, o);
    const float rs = rsqrtf(s2 * (1.f / 256.f) + 1e-5f);
    float gg[8], bb[8];
    ld8(gg, g, lane);
    ld8(bb, b, lane);
    #pragma unroll
    for (int i = 0; i < 8; i++) v[i] = gg[i] * v[i] * rs + bb[i];
    uint4 hi, lo;
    split_pack8(v, hi, lo);
    uint4* base = reinterpret_cast<uint4*>(Aext + (size_t)row * 512 + lane * 8);
    base[0]  = hi;
    base[32] = lo;
}

// ------------------------- relay projections (1024 thr, k-split) ---------------
__global__ __launch_bounds__(1024) void small3_k(
    const float* __restrict__ x,
    const float* __restrict__ WK, const float* __restrict__ bK,
    const float* __restrict__ WV, const float* __restrict__ bV,
    const float* __restrict__ WQ, const float* __restrict__ bQ,
    float* __restrict__ ak, float* __restrict__ av, float* __restrict__ q2)
{
    __shared__ float xr[Hh];
    __shared__ float part[3][Hh];
    const int b = blockIdx.x, which = blockIdx.y;
    const int col = threadIdx.x & 255, kq = threadIdx.x >> 8;   // 4 k-quarters
    const float* W; const float* bias; float* out;
    if (which == 0)      { W = WK; bias = bK; out = ak; }
    else if (which == 1) { W = WV; bias = bV; out = av; }
    else                 { W = WQ; bias = bQ; out = q2; }
    if (threadIdx.x < Hh) xr[threadIdx.x] = x[b * Hh + threadIdx.x];
    __syncthreads();
    float acc = 0.f;
    const float* wp = W + (size_t)(kq * 64) * Hh + col;
    #pragma unroll 16
    for (int j = 0; j < 64; j++) acc += xr[kq * 64 + j] * wp[(size_t)j * Hh];
    if (kq > 0) part[kq - 1][col] = acc;
    __syncthreads();
    if (kq == 0)
        out[b * Hh + col] = acc + part[0][col] + part[1][col] + part[2][col] + bias[col];
}

// ------------------------- relay WO (1024 thr, k-split) + leaky ----------------
__global__ __launch_bounds__(1024) void small_gemm(
    const float* __restrict__ x, const float* __restrict__ W,
    const float* __restrict__ bias, float* __restrict__ out)
{
    __shared__ float xr[Hh];
    __shared__ float part[3][Hh];
    const int b = blockIdx.x;
    const int col = threadIdx.x & 255, kq = threadIdx.x >> 8;
    if (threadIdx.x < Hh) xr[threadIdx.x] = x[b * Hh + threadIdx.x];
    __syncthreads();
    float acc = 0.f;
    const float* wp = W + (size_t)(kq * 64) * Hh + col;
    #pragma unroll 16
    for (int j = 0; j < 64; j++) acc += xr[kq * 64 + j] * wp[(size_t)j * Hh];
    if (kq > 0) part[kq - 1][col] = acc;
    __syncthreads();
    if (kq == 0) {
        float r = acc + part[0][col] + part[1][col] + part[2][col] + bias[col];
        r = r > 0.f ? r : 0.01f * r;
        out[b * Hh + col] = r;
    }
}

// ------------------------- msa1 attention (warp/row) -> Aext split -------------
__global__ __launch_bounds__(256) void attn1w_k(
    const float* __restrict__ q, const float* __restrict__ k,
    const float* __restrict__ ak, const float* __restrict__ av,
    __nv_bfloat16* __restrict__ Aext)
{
    const int lane = threadIdx.x & 31;
    const int row = blockIdx.x * 8 + (threadIdx.x >> 5);   // b*512 + l
    const int b = row >> 9, l = row & (Ll - 1);

    float qv[8], kc[8], km[8], kp[8], k0[8], v0[8];
    ld8(qv, q + (size_t)row * 256, lane);
    ld8(kc, k + (size_t)row * 256, lane);
    ld8(k0, ak + (size_t)b * 256, lane);
    ld8(v0, av + (size_t)b * 256, lane);
    if (l > 0) {
        ld8(km, k + (size_t)(row - 1) * 256, lane);
    } else {
        zero8(km);
    }
    if (l < Ll - 1) {
        ld8(kp, k + (size_t)(row + 1) * 256, lane);
    } else {
        zero8(kp);
    }

    float s0 = 0.f, s1 = 0.f, s2 = 0.f, s3 = 0.f;
    #pragma unroll
    for (int i = 0; i < 8; i++) {
        s0 += qv[i] * k0[i];
        s1 += qv[i] * km[i];
        s2 += qv[i] * kc[i];
        s3 += qv[i] * kp[i];
    }
    #pragma unroll
    for (int o = 1; o <= 2; o <<= 1) {
        s0 += __shfl_xor_sync(0xffffffffu, s0, o);
        s1 += __shfl_xor_sync(0xffffffffu, s1, o);
        s2 += __shfl_xor_sync(0xffffffffu, s2, o);
        s3 += __shfl_xor_sync(0xffffffffu, s3, o);
    }
    const float sc = 0.17677669529663687f;   // 1/sqrt(32)
    s0 *= sc; s1 *= sc; s2 *= sc; s3 *= sc;
    float mx = fmaxf(fmaxf(s0, s1), fmaxf(s2, s3));
    float e0 = expf(s0 - mx), e1 = expf(s1 - mx), e2 = expf(s2 - mx), e3 = expf(s3 - mx);
    const float inv = 1.f / (e0 + e1 + e2 + e3);
    // NOTE: window values come from K (faithful to reference bug)
    float ov[8];
    #pragma unroll
    for (int i = 0; i < 8; i++)
        ov[i] = (e0 * v0[i] + e1 * km[i] + e2 * kc[i] + e3 * kp[i]) * inv;
    uint4 hi, lo;
    split_pack8(ov, hi, lo);
    uint4* base = reinterpret_cast<uint4*>(Aext + (size_t)row * 512 + lane * 8);
    base[0]  = hi;
    base[32] = lo;
}

// ------------------------- y = [relay; nodes] + fold mask ----------------------
// Builds y from PRE-mask nodes (reference semantics), then applies the mask to
// x0 in place (nodes[data==1] = 0) — removes the separate mask_k launch.
__global__ __launch_bounds__(256) void convy8m_k(
    const float* __restrict__ relay, float* __restrict__ nodes,
    const int* __restrict__ data, __nv_bfloat16* __restrict__ Aext)
{
    const int lane = threadIdx.x & 31;
    const int r = blockIdx.x * 8 + (threadIdx.x >> 5);    // 0..16511
    float v[8];
    zero8(v);
    int tok = -1;
    if (r < Bb * L1) {
        const int b = r / L1, l1 = r - b * L1;
        if (l1 == 0) {
            ld8(v, relay + b * Hh, lane);
        } else {
            tok = b * Ll + l1 - 1;
            ld8(v, nodes + (size_t)tok * Hh, lane);
        }
    }
    uint4 hi, lo;
    split_pack8(v, hi, lo);
    uint4* base = reinterpret_cast<uint4*>(Aext + (size_t)r * 512 + lane * 8);
    base[0]  = hi;
    base[32] = lo;
    // fold mask: zero this node row if data == 1
    if (tok >= 0 && data[tok] == 1) {
        float4 z = make_float4(0.f, 0.f, 0.f, 0.f);
        float4* np = reinterpret_cast<float4*>(nodes + (size_t)tok * Hh);
        np[lane * 2]     = z;
        np[lane * 2 + 1] = z;
    }
}

// ------------------------- msa2 attention --------------------------------------
__global__ __launch_bounds__(256) void attn2_k(
    const float* __restrict__ q2, const float* __restrict__ k2,
    const float* __restrict__ v2, float* __restrict__ att2)
{
    const int b = blockIdx.x, n = blockIdx.y;
    const int w = threadIdx.x >> 5, d = threadIdx.x & 31;
    const int t = threadIdx.x;
    __shared__ float sc[L1];
    __shared__ float red[8];
    __shared__ float part[8][32];
    const float qv = q2[b * Hh + n * HD + d];
    for (int j = w; j < L1; j += 8) {
        float p = qv * k2[(b * L1 + j) * Hh + n * HD + d];
        #pragma unroll
        for (int o = 16; o; o >>= 1) p += __shfl_xor_sync(0xffffffffu, p, o);
        if (d == 0) sc[j] = p * 0.17677669529663687f;
    }
    __syncthreads();
    float mx = -3.4e38f;
    for (int j = t; j < L1; j += 256) mx = fmaxf(mx, sc[j]);
    #pragma unroll
    for (int o = 16; o; o >>= 1) mx = fmaxf(mx, __shfl_xor_sync(0xffffffffu, mx, o));
    if (d == 0) red[w] = mx;
    __syncthreads();
    float gmx = red[0];
    #pragma unroll
    for (int r = 1; r < 8; r++) gmx = fmaxf(gmx, red[r]);
    __syncthreads();
    float ls = 0.f;
    for (int j = t; j < L1; j += 256) { float e = expf(sc[j] - gmx); sc[j] = e; ls += e; }
    #pragma unroll
    for (int o = 16; o; o >>= 1) ls += __shfl_xor_sync(0xffffffffu, ls, o);
    if (d == 0) red[w] = ls;
    __syncthreads();
    float tot = 0.f;
    #pragma unroll
    for (int r = 0; r < 8; r++) tot += red[r];
    const float inv = 1.f / tot;
    float acc = 0.f;
    for (int j = w; j < L1; j += 8) acc += sc[j] * v2[(b * L1 + j) * Hh + n * HD + d];
    part[w][d] = acc;
    __syncthreads();
    if (w == 0) {
        float s = 0.f;
        #pragma unroll
        for (int r = 0; r < 8; r++) s += part[r][d];
        att2[b * Hh + n * HD + d] = s * inv;
    }
}

// ------------------------- final -----------------------------------------------
__global__ __launch_bounds__(256) void final_k(
    const float* __restrict__ nodes, const float* __restrict__ relay,
    float* __restrict__ out)
{
    const int b = blockIdx.x, t = threadIdx.x;
    float m = -3.4e38f;
    for (int l = 0; l < Ll; l++) m = fmaxf(m, nodes[(b * Ll + l) * Hh + t]);
    out[b * Hh + t] = 0.5f * m + 0.5f * relay[b * Hh + t];
}

// ------------------------- launch ----------------------------------------------
extern "C" void kernel_launch(void* const* d_in, const int* in_sizes, int n_in,
                              void* d_out, int out_size)
{
    (void)in_sizes; (void)n_in; (void)out_size;
    const int*   data     = (const int*)  d_in[0];
    const float* emb      = (const float*)d_in[1];
    const float* emb_fc_W = (const float*)d_in[2];
    const float* emb_fc_b = (const float*)d_in[3];
    const float* pos_emb  = (const float*)d_in[4];
    const float* ln_g     = (const float*)d_in[5];
    const float* ln_b     = (const float*)d_in[6];
    const float* r_WQ = (const float*)d_in[7];
    const float* r_bQ = (const float*)d_in[8];
    const float* r_WK = (const float*)d_in[9];
    const float* r_bK = (const float*)d_in[10];
    const float* r_WV = (const float*)d_in[11];
    const float* r_bV = (const float*)d_in[12];
    const float* r_WO = (const float*)d_in[13];
    const float* r_bO = (const float*)d_in[14];
    const float* s_WQ = (const float*)d_in[15];
    const float* s_bQ = (const float*)d_in[16];
    const float* s_WK = (const float*)d_in[17];
    const float* s_bK = (const float*)d_in[18];
    const float* s_WV = (const float*)d_in[19];
    const float* s_bV = (const float*)d_in[20];
    const float* s_WO = (const float*)d_in[21];
    const float* s_bO = (const float*)d_in[22];

    float *x0, *q, *k, *k2, *v2, *relay, *ak, *av, *q2, *att2;
    __nv_bfloat16 *Aext, *Wext;
    cudaGetSymbolAddress((void**)&x0,   g_x0);
    cudaGetSymbolAddress((void**)&q,    g_q);
    cudaGetSymbolAddress((void**)&k,    g_k);
    cudaGetSymbolAddress((void**)&k2,   g_k2);
    cudaGetSymbolAddress((void**)&v2,   g_v2);
    cudaGetSymbolAddress((void**)&relay,g_relay);
    cudaGetSymbolAddress((void**)&ak,   g_ak);
    cudaGetSymbolAddress((void**)&av,   g_av);
    cudaGetSymbolAddress((void**)&q2,   g_q2);
    cudaGetSymbolAddress((void**)&att2, g_att2);
    cudaGetSymbolAddress((void**)&Aext, g_Aext);
    cudaGetSymbolAddress((void**)&Wext, g_Wext);

    cudaFuncSetAttribute(gemm_hmma<0,1>, cudaFuncAttributeMaxDynamicSharedMemorySize, GSMEM);
    cudaFuncSetAttribute(gemm_hmma<1,0>, cudaFuncAttributeMaxDynamicSharedMemorySize, GSMEM);

    const int M1 = Bb * Ll;      // 16384
    const int M2 = Bb * L1;      // 16416
    const size_t WMAT = (size_t)256 * 512;

    // rotated schedule: gemm_hmma<0,1> is the 4th kernel launch (ncu capture slot)
    embed_k<<<Bb * Ll / 32, 256>>>(data, emb, emb_fc_W, emb_fc_b, pos_emb, x0);    // 1
    convW_k<<<dim3(30, 8), 256>>>(r_WQ, r_WK, r_WO, s_WK, s_WV, Wext);             // 2
    ln8_k<<<M1 / 8, 256>>>(x0, ln_g, ln_b, Aext);                                  // 3 (iter 0)
    gemm_hmma<0,1><<<dim3(128, 4), 256, GSMEM>>>(Aext, Wext, r_bQ, q,              // 4 (iter 0)
                                                 Wext + WMAT, r_bK, k, M1);
    relay_init_k<<<Bb, 1024>>>(x0, relay);                                         // 5

    for (int i = 0; i < NITER; i++) {
        const int bo = i * Hh;
        const __nv_bfloat16* wO  = Wext + (size_t)(i * 5 + 2) * WMAT;
        const __nv_bfloat16* wK2 = Wext + (size_t)(i * 5 + 3) * WMAT;
        const __nv_bfloat16* wV2 = Wext + (size_t)(i * 5 + 4) * WMAT;

        small3_k<<<dim3(Bb, 3), 1024>>>(relay,
                                        r_WK + i * Hh * Hh, r_bK + bo,
                                        r_WV + i * Hh * Hh, r_bV + bo,
                                        s_WQ + i * Hh * Hh, s_bQ + bo,
                                        ak, av, q2);
        attn1w_k<<<M1 / 8, 256>>>(q, k, ak, av, Aext);
        gemm_hmma<1,0><<<dim3(128, 2), 256, GSMEM>>>(Aext, wO, r_bO + bo, x0,
                                                     nullptr, nullptr, nullptr, M1);
        convy8m_k<<<AROWS / 8, 256>>>(relay, x0, data, Aext);
        gemm_hmma<0,1><<<dim3(ATILES, 4), 256, GSMEM>>>(Aext, wK2, s_bK + bo, k2,
                                                        wV2, s_bV + bo, v2, M2);
        attn2_k<<<dim3(Bb, NH), 256>>>(q2, k2, v2, att2);
        small_gemm<<<Bb, 1024>>>(att2, s_WO + i * Hh * Hh, s_bO + bo, relay);
        if (i + 1 < NITER) {
            const int bo1 = (i + 1) * Hh;
            const __nv_bfloat16* wQ1 = Wext + (size_t)((i + 1) * 5 + 0) * WMAT;
            const __nv_bfloat16* wK1 = Wext + (size_t)((i + 1) * 5 + 1) * WMAT;
            ln8_k<<<M1 / 8, 256>>>(x0, ln_g + bo1, ln_b + bo1, Aext);
            gemm_hmma<0,1><<<dim3(128, 4), 256, GSMEM>>>(Aext, wQ1, r_bQ + bo1, q,
                                                         wK1, r_bK + bo1, k, M1);
        }
    }
    final_k<<<Bb, 256>>>(x0, relay, (float*)d_out);
}

// round 16
// speedup vs baseline: 4.7334x; 1.0437x over previous
#include <cuda_runtime.h>
#include <cuda_bf16.h>
#include <math.h>
#include <stdint.h>

#define Bb   32
#define Ll   512
#define Hh   256
#define EMB  300
#define NH   8
#define HD   32
#define L1   513
#define NITER 6

#define ATILES 129
#define AROWS  (ATILES*128)      // 16512
#define TSTR   80                // smem row stride bytes (32 bf16 + 8 pad)
#define TILE   (128*TSTR)        // 10240 B per tile
#define STGB   (4*TILE)          // 40960 B per stage (A_hi, A_lo, B_hi, B_lo)
#define NSTG   2
#define GSMEM  (NSTG*STGB)       // 81920 B

// ------------------------- scratch (static, no allocs) -------------------------
__device__ float g_x0 [Bb*Ll*Hh];
__device__ float g_q  [Bb*Ll*Hh];
__device__ float g_k  [Bb*Ll*Hh];
__device__ float g_k2 [Bb*L1*Hh];
__device__ float g_v2 [Bb*L1*Hh];
__device__ float g_relay[Bb*Hh];
__device__ float g_ak [Bb*Hh];
__device__ float g_av [Bb*Hh];
__device__ float g_q2 [Bb*Hh];
__device__ float g_att2[Bb*Hh];
__device__ __nv_bfloat16 g_Aext[(size_t)AROWS*512];       // [row][ hi(256) | lo(256) ]
__device__ __nv_bfloat16 g_Wext[(size_t)30*256*512];      // per mat: [n][ hi | lo ] (k-minor)

// ------------------------- PTX helpers -----------------------------------------
__device__ __forceinline__ uint32_t smem_u32(const void* p) {
    uint32_t a;
    asm("{ .reg .u64 t; cvta.to.shared.u64 t, %1; cvt.u32.u64 %0, t; }"
        : "=r"(a) : "l"(p));
    return a;
}
#define CPA(dst, src) \
    asm volatile("cp.async.cg.shared.global [%0], [%1], 16;" :: "r"(dst), "l"(src))
#define CP_COMMIT() asm volatile("cp.async.commit_group;" ::: "memory")
#define LDM4(r0, r1, r2, r3, a) \
    asm volatile("ldmatrix.sync.aligned.m8n8.x4.shared.b16 {%0,%1,%2,%3}, [%4];" \
                 : "=r"(r0), "=r"(r1), "=r"(r2), "=r"(r3) : "r"(a))
#define MMA16816(d, a, b0, b1) \
    asm volatile("mma.sync.aligned.m16n8k16.row.col.f32.bf16.bf16.f32 " \
                 "{%0,%1,%2,%3}, {%4,%5,%6,%7}, {%8,%9}, {%0,%1,%2,%3};" \
                 : "+f"((d)[0]), "+f"((d)[1]), "+f"((d)[2]), "+f"((d)[3]) \
                 : "r"((a)[0]), "r"((a)[1]), "r"((a)[2]), "r"((a)[3]), \
                   "r"(b0), "r"(b1))

// pack 8 floats -> 8 hi bf16 (uint4) + 8 lo bf16 (uint4)
__device__ __forceinline__ void split_pack8(
    const float* v, uint4& hi, uint4& lo)
{
    uint32_t h[4], l[4];
    #pragma unroll
    for (int p = 0; p < 4; p++) {
        __nv_bfloat16 h0 = __float2bfloat16(v[2*p]);
        __nv_bfloat16 h1 = __float2bfloat16(v[2*p+1]);
        __nv_bfloat16 l0 = __float2bfloat16(v[2*p]   - __bfloat162float(h0));
        __nv_bfloat16 l1 = __float2bfloat16(v[2*p+1] - __bfloat162float(h1));
        h[p] = (uint32_t)__bfloat16_as_ushort(h0) | ((uint32_t)__bfloat16_as_ushort(h1) << 16);
        l[p] = (uint32_t)__bfloat16_as_ushort(l0) | ((uint32_t)__bfloat16_as_ushort(l1) << 16);
    }
    hi = make_uint4(h[0], h[1], h[2], h[3]);
    lo = make_uint4(l[0], l[1], l[2], l[3]);
}

__device__ __forceinline__ void ld8(float* v, const float* p, int lane) {
    const float4* fp = reinterpret_cast<const float4*>(p);
    float4 a0 = fp[lane * 2], a1 = fp[lane * 2 + 1];
    v[0]=a0.x; v[1]=a0.y; v[2]=a0.z; v[3]=a0.w;
    v[4]=a1.x; v[5]=a1.y; v[6]=a1.z; v[7]=a1.w;
}

__device__ __forceinline__ void zero8(float* v) {
    #pragma unroll
    for (int i = 0; i < 8; i++) v[i] = 0.f;
}

// ------------------------- HMMA GEMM (dense 3-term chunks) ---------------------
// C[M,256] = A[M,256]@W[256,256] + bias via 3-term bf16 split.
// 8 chunks of k=32; each chunk loads A_hi/A_lo/B_hi/B_lo tiles (40KB) and runs
// all 3 terms (96 MMAs): t0=A_hi*B_hi, t1=A_lo*B_hi, t2=A_hi*B_lo.
// 256 threads = 8 warps (4m x 2n), warp tile 32x64, 2-stage cp.async pipeline.
// MODE 0: store; MODE 1: C += leaky_relu(.)
// DUAL 1: grid.y 0..3 -> {W0 n0, W0 n1, W1 n0, W1 n1}
template <int MODE, int DUAL>
__global__ __launch_bounds__(256, 2) void gemm_hmma(
    const __nv_bfloat16* __restrict__ Aext,
    const __nv_bfloat16* __restrict__ W0, const float* __restrict__ b0,
    float* __restrict__ C0,
    const __nv_bfloat16* __restrict__ W1, const float* __restrict__ b1,
    float* __restrict__ C1, int M)
{
    extern __shared__ char smem[];
    const uint32_t sb = smem_u32(smem);
    const int t = threadIdx.x, lane = t & 31, wid = t >> 5;
    const int mw = wid >> 1, nw = wid & 1;
    const int ny = blockIdx.y;
    const __nv_bfloat16* W;  const float* bias;  float* C;
    if (DUAL && ny >= 2) { W = W1; bias = b1; C = C1; }
    else                 { W = W0; bias = b0; C = C0; }
    const int n0 = (DUAL ? (ny & 1) : ny) * 128;
    const int m0 = blockIdx.x * 128;

    const char* Ag = (const char*)(Aext + (size_t)m0 * 512);
    const char* Bg = (const char*)(W + (size_t)n0 * 512);

    const int lr = t >> 2;
    const int lq = (t & 3) * 16;

    const uint32_t aoff = (uint32_t)(mw * 32 + (lane & 15)) * TSTR
                        + (uint32_t)((lane >> 4) & 1) * 16;
    const uint32_t boff = (uint32_t)(nw * 64 + (lane & 7) + ((lane >> 4) & 1) * 8) * TSTR
                        + (uint32_t)((lane >> 3) & 1) * 16;

    float acc[2][8][4];
    #pragma unroll
    for (int i = 0; i < 2; i++)
        #pragma unroll
        for (int j = 0; j < 8; j++)
            #pragma unroll
            for (int c = 0; c < 4; c++) acc[i][j][c] = 0.f;

    // per chunk: 4 tiles (A_hi, A_lo at +512B row offset; B_hi, B_lo likewise)
    #define ISSUE_LOAD(ch, buf) do {                                              \
        const int cO = (ch) * 64;                                                 \
        const uint32_t s0 = sb + (buf) * STGB;                                    \
        CPA(s0 + lr * TSTR + lq,                 Ag + (size_t)lr * 1024 + cO + lq);       \
        CPA(s0 + (lr+64) * TSTR + lq,            Ag + (size_t)(lr+64) * 1024 + cO + lq);  \
        CPA(s0 + TILE + lr * TSTR + lq,          Ag + (size_t)lr * 1024 + 512 + cO + lq); \
        CPA(s0 + TILE + (lr+64) * TSTR + lq,     Ag + (size_t)(lr+64) * 1024 + 512 + cO + lq); \
        CPA(s0 + 2*TILE + lr * TSTR + lq,        Bg + (size_t)lr * 1024 + cO + lq);       \
        CPA(s0 + 2*TILE + (lr+64) * TSTR + lq,   Bg + (size_t)(lr+64) * 1024 + cO + lq);  \
        CPA(s0 + 3*TILE + lr * TSTR + lq,        Bg + (size_t)lr * 1024 + 512 + cO + lq); \
        CPA(s0 + 3*TILE + (lr+64) * TSTR + lq,   Bg + (size_t)(lr+64) * 1024 + 512 + cO + lq); \
        CP_COMMIT();                                                              \
    } while (0)

    ISSUE_LOAD(0, 0);
    ISSUE_LOAD(1, 1);
    for (int ch = 0; ch < 8; ch++) {
        if (ch < 7) {
            asm volatile("cp.async.wait_group 1;" ::: "memory");
        } else {
            asm volatile("cp.async.wait_group 0;" ::: "memory");
        }
        __syncthreads();
        const uint32_t s0  = sb + (ch & 1) * STGB;
        const uint32_t sAh = s0, sAl = s0 + TILE, sBh = s0 + 2*TILE, sBl = s0 + 3*TILE;
        #pragma unroll
        for (int k16 = 0; k16 < 2; k16++) {
            uint32_t ah[2][4], al[2][4], bf[4][4];
            // A_hi + B_hi fragments
            LDM4(ah[0][0], ah[0][1], ah[0][2], ah[0][3], sAh + aoff + k16 * 32);
            LDM4(ah[1][0], ah[1][1], ah[1][2], ah[1][3], sAh + aoff + 16 * TSTR + k16 * 32);
            #pragma unroll
            for (int g = 0; g < 4; g++)
                LDM4(bf[g][0], bf[g][1], bf[g][2], bf[g][3],
                     sBh + boff + g * 16 * TSTR + k16 * 32);
            // t0: A_hi x B_hi
            #pragma unroll
            for (int mi = 0; mi < 2; mi++)
                #pragma unroll
                for (int g = 0; g < 4; g++) {
                    MMA16816(acc[mi][2 * g],     ah[mi], bf[g][0], bf[g][1]);
                    MMA16816(acc[mi][2 * g + 1], ah[mi], bf[g][2], bf[g][3]);
                }
            // t1: A_lo x B_hi (reuse bf)
            LDM4(al[0][0], al[0][1], al[0][2], al[0][3], sAl + aoff + k16 * 32);
            LDM4(al[1][0], al[1][1], al[1][2], al[1][3], sAl + aoff + 16 * TSTR + k16 * 32);
            #pragma unroll
            for (int mi = 0; mi < 2; mi++)
                #pragma unroll
                for (int g = 0; g < 4; g++) {
                    MMA16816(acc[mi][2 * g],     al[mi], bf[g][0], bf[g][1]);
                    MMA16816(acc[mi][2 * g + 1], al[mi], bf[g][2], bf[g][3]);
                }
            // t2: A_hi x B_lo (reload bf)
            #pragma unroll
            for (int g = 0; g < 4; g++)
                LDM4(bf[g][0], bf[g][1], bf[g][2], bf[g][3],
                     sBl + boff + g * 16 * TSTR + k16 * 32);
            #pragma unroll
            for (int mi = 0; mi < 2; mi++)
                #pragma unroll
                for (int g = 0; g < 4; g++) {
                    MMA16816(acc[mi][2 * g],     ah[mi], bf[g][0], bf[g][1]);
                    MMA16816(acc[mi][2 * g + 1], ah[mi], bf[g][2], bf[g][3]);
                }
        }
        __syncthreads();
        if (ch + 2 < 8) ISSUE_LOAD(ch + 2, ch & 1);
    }

    // epilogue
    const int tr = lane >> 2, tc = (lane & 3) * 2;
    const float* bp = bias + n0 + nw * 64;
    #pragma unroll
    for (int mi = 0; mi < 2; mi++) {
        #pragma unroll
        for (int h = 0; h < 2; h++) {
            const int row = m0 + mw * 32 + mi * 16 + tr + h * 8;
            if (row < M) {
                float* cp = C + (size_t)row * 256 + n0 + nw * 64;
                #pragma unroll
                for (int ni = 0; ni < 8; ni++) {
                    const int col = ni * 8 + tc;
                    float v0 = acc[mi][ni][h * 2]     + bp[col];
                    float v1 = acc[mi][ni][h * 2 + 1] + bp[col + 1];
                    if (MODE) {
                        v0 = v0 > 0.f ? v0 : 0.01f * v0;
                        v1 = v1 > 0.f ? v1 : 0.01f * v1;
                        float2 o = *reinterpret_cast<const float2*>(cp + col);
                        v0 += o.x; v1 += o.y;
                    }
                    *reinterpret_cast<float2*>(cp + col) = make_float2(v0, v1);
                }
            }
        }
    }
}

// ------------------------- weight conversion (30 mats, transposed split) -------
__global__ __launch_bounds__(256) void convW_k(
    const float* __restrict__ W0, const float* __restrict__ W1,
    const float* __restrict__ W2, const float* __restrict__ W3,
    const float* __restrict__ W4, __nv_bfloat16* __restrict__ Wext)
{
    const int mat = blockIdx.x, ng = blockIdx.y, t = threadIdx.x;
    const int it = mat / 5, which = mat % 5;
    const float* W;
    switch (which) {
        case 0: W = W0; break; case 1: W = W1; break; case 2: W = W2; break;
        case 3: W = W3; break; default: W = W4; break;
    }
    W += (size_t)it * Hh * Hh;
    __shared__ float tile[32][33];
    const int n0 = ng * 32;
    for (int kt = 0; kt < 8; kt++) {
        const int k0 = kt * 32;
        __syncthreads();
        #pragma unroll
        for (int p = 0; p < 4; p++) {
            const int kk = (t >> 5) + p * 8, nn = t & 31;
            tile[kk][nn] = W[(k0 + kk) * 256 + n0 + nn];
        }
        __syncthreads();
        #pragma unroll
        for (int p = 0; p < 4; p++) {
            const int nn = (t >> 5) + p * 8, kk = t & 31;
            const float v = tile[kk][nn];
            const size_t base = ((size_t)mat * 256 + n0 + nn) * 512 + k0 + kk;
            __nv_bfloat16 h = __float2bfloat16(v);
            Wext[base]       = h;
            Wext[base + 256] = __float2bfloat16(v - __bfloat162float(h));
        }
    }
}

// ------------------------- embedding -------------------------------------------
__global__ __launch_bounds__(256) void embed_k(
    const int* __restrict__ data, const float* __restrict__ emb,
    const float* __restrict__ W, const float* __restrict__ bias,
    const float* __restrict__ pos, float* __restrict__ x0)
{
    __shared__ float As[32][EMB];
    __shared__ int   toks[32];
    const int r0 = blockIdx.x * 32;
    const int t  = threadIdx.x;
    if (t < 32) toks[t] = data[r0 + t];
    __syncthreads();
    for (int i = t; i < 32 * EMB; i += 256) {
        int r = i / EMB, e = i - r * EMB;
        As[r][e] = emb[toks[r] * EMB + e];
    }
    __syncthreads();
    float acc[32];
    #pragma unroll
    for (int r = 0; r < 32; r++) acc[r] = 0.f;
    for (int e = 0; e < EMB; e++) {
        float w = W[e * Hh + t];
        #pragma unroll
        for (int r = 0; r < 32; r++) acc[r] += As[r][e] * w;
    }
    const float bs = bias[t];
    #pragma unroll
    for (int r = 0; r < 32; r++) {
        int row = r0 + r;
        int l   = row & (Ll - 1);
        x0[row * Hh + t] = acc[r] + bs + pos[l * Hh + t];
    }
}

// ------------------------- relay init (1024 thr, l-split) ----------------------
__global__ __launch_bounds__(1024) void relay_init_k(
    const float* __restrict__ x0, float* __restrict__ relay)
{
    __shared__ float part[3][Hh];
    const int b = blockIdx.x;
    const int col = threadIdx.x & 255, lq = threadIdx.x >> 8;   // 4 slices of 128
    float s = 0.f;
    #pragma unroll 16
    for (int l = lq * 128; l < lq * 128 + 128; l++)
        s += x0[((size_t)b * Ll + l) * Hh + col];
    if (lq > 0) part[lq - 1][col] = s;
    __syncthreads();
    if (lq == 0)
        relay[b * Hh + col] = (s + part[0][col] + part[1][col] + part[2][col]) * (1.f / Ll);
}

// ------------------------- layernorm (warp/row) -> Aext split ------------------
__global__ __launch_bounds__(256) void ln8_k(
    const float* __restrict__ x, const float* __restrict__ g,
    const float* __restrict__ b, __nv_bfloat16* __restrict__ Aext)
{
    const int lane = threadIdx.x & 31;
    const int row = blockIdx.x * 8 + (threadIdx.x >> 5);
    float v[8];
    ld8(v, x + (size_t)row * 256, lane);
    float s = 0.f;
    #pragma unroll
    for (int i = 0; i < 8; i++) s += v[i];
    #pragma unroll
    for (int o = 16; o; o >>= 1) s += __shfl_xor_sync(0xffffffffu, s, o);
    const float mu = s * (1.f / 256.f);
    float s2 = 0.f;
    #pragma unroll
    for (int i = 0; i < 8; i++) { v[i] -= mu; s2 += v[i] * v[i]; }
    #pragma unroll
    for (int o = 16; o; o >>= 1) s2 += __shfl_xor_sync(0xffffffffu, s2, o);
    const float rs = rsqrtf(s2 * (1.f / 256.f) + 1e-5f);
    float gg[8], bb[8];
    ld8(gg, g, lane);
    ld8(bb, b, lane);
    #pragma unroll
    for (int i = 0; i < 8; i++) v[i] = gg[i] * v[i] * rs + bb[i];
    uint4 hi, lo;
    split_pack8(v, hi, lo);
    uint4* base = reinterpret_cast<uint4*>(Aext + (size_t)row * 512 + lane * 8);
    base[0]  = hi;
    base[32] = lo;
}

// ------------------------- relay projections (1024 thr, k-split) ---------------
__global__ __launch_bounds__(1024) void small3_k(
    const float* __restrict__ x,
    const float* __restrict__ WK, const float* __restrict__ bK,
    const float* __restrict__ WV, const float* __restrict__ bV,
    const float* __restrict__ WQ, const float* __restrict__ bQ,
    float* __restrict__ ak, float* __restrict__ av, float* __restrict__ q2)
{
    __shared__ float xr[Hh];
    __shared__ float part[3][Hh];
    const int b = blockIdx.x, which = blockIdx.y;
    const int col = threadIdx.x & 255, kq = threadIdx.x >> 8;   // 4 k-quarters
    const float* W; const float* bias; float* out;
    if (which == 0)      { W = WK; bias = bK; out = ak; }
    else if (which == 1) { W = WV; bias = bV; out = av; }
    else                 { W = WQ; bias = bQ; out = q2; }
    if (threadIdx.x < Hh) xr[threadIdx.x] = x[b * Hh + threadIdx.x];
    __syncthreads();
    float acc = 0.f;
    const float* wp = W + (size_t)(kq * 64) * Hh + col;
    #pragma unroll 16
    for (int j = 0; j < 64; j++) acc += xr[kq * 64 + j] * wp[(size_t)j * Hh];
    if (kq > 0) part[kq - 1][col] = acc;
    __syncthreads();
    if (kq == 0)
        out[b * Hh + col] = acc + part[0][col] + part[1][col] + part[2][col] + bias[col];
}

// ------------------------- relay WO (1024 thr, k-split) + leaky ----------------
__global__ __launch_bounds__(1024) void small_gemm(
    const float* __restrict__ x, const float* __restrict__ W,
    const float* __restrict__ bias, float* __restrict__ out)
{
    __shared__ float xr[Hh];
    __shared__ float part[3][Hh];
    const int b = blockIdx.x;
    const int col = threadIdx.x & 255, kq = threadIdx.x >> 8;
    if (threadIdx.x < Hh) xr[threadIdx.x] = x[b * Hh + threadIdx.x];
    __syncthreads();
    float acc = 0.f;
    const float* wp = W + (size_t)(kq * 64) * Hh + col;
    #pragma unroll 16
    for (int j = 0; j < 64; j++) acc += xr[kq * 64 + j] * wp[(size_t)j * Hh];
    if (kq > 0) part[kq - 1][col] = acc;
    __syncthreads();
    if (kq == 0) {
        float r = acc + part[0][col] + part[1][col] + part[2][col] + bias[col];
        r = r > 0.f ? r : 0.01f * r;
        out[b * Hh + col] = r;
    }
}

// ------------------------- msa1 attention (warp/row) -> Aext split -------------
__global__ __launch_bounds__(256) void attn1w_k(
    const float* __restrict__ q, const float* __restrict__ k,
    const float* __restrict__ ak, const float* __restrict__ av,
    __nv_bfloat16* __restrict__ Aext)
{
    const int lane = threadIdx.x & 31;
    const int row = blockIdx.x * 8 + (threadIdx.x >> 5);   // b*512 + l
    const int b = row >> 9, l = row & (Ll - 1);

    float qv[8], kc[8], km[8], kp[8], k0[8], v0[8];
    ld8(qv, q + (size_t)row * 256, lane);
    ld8(kc, k + (size_t)row * 256, lane);
    ld8(k0, ak + (size_t)b * 256, lane);
    ld8(v0, av + (size_t)b * 256, lane);
    if (l > 0) {
        ld8(km, k + (size_t)(row - 1) * 256, lane);
    } else {
        zero8(km);
    }
    if (l < Ll - 1) {
        ld8(kp, k + (size_t)(row + 1) * 256, lane);
    } else {
        zero8(kp);
    }

    float s0 = 0.f, s1 = 0.f, s2 = 0.f, s3 = 0.f;
    #pragma unroll
    for (int i = 0; i < 8; i++) {
        s0 += qv[i] * k0[i];
        s1 += qv[i] * km[i];
        s2 += qv[i] * kc[i];
        s3 += qv[i] * kp[i];
    }
    #pragma unroll
    for (int o = 1; o <= 2; o <<= 1) {
        s0 += __shfl_xor_sync(0xffffffffu, s0, o);
        s1 += __shfl_xor_sync(0xffffffffu, s1, o);
        s2 += __shfl_xor_sync(0xffffffffu, s2, o);
        s3 += __shfl_xor_sync(0xffffffffu, s3, o);
    }
    const float sc = 0.17677669529663687f;   // 1/sqrt(32)
    s0 *= sc; s1 *= sc; s2 *= sc; s3 *= sc;
    float mx = fmaxf(fmaxf(s0, s1), fmaxf(s2, s3));
    float e0 = expf(s0 - mx), e1 = expf(s1 - mx), e2 = expf(s2 - mx), e3 = expf(s3 - mx);
    const float inv = 1.f / (e0 + e1 + e2 + e3);
    // NOTE: window values come from K (faithful to reference bug)
    float ov[8];
    #pragma unroll
    for (int i = 0; i < 8; i++)
        ov[i] = (e0 * v0[i] + e1 * km[i] + e2 * kc[i] + e3 * kp[i]) * inv;
    uint4 hi, lo;
    split_pack8(ov, hi, lo);
    uint4* base = reinterpret_cast<uint4*>(Aext + (size_t)row * 512 + lane * 8);
    base[0]  = hi;
    base[32] = lo;
}

// ------------------------- y = [relay; nodes] + fold mask ----------------------
// Builds y from PRE-mask nodes (reference semantics), then applies the mask to
// x0 in place (nodes[data==1] = 0) — removes the separate mask_k launch.
__global__ __launch_bounds__(256) void convy8m_k(
    const float* __restrict__ relay, float* __restrict__ nodes,
    const int* __restrict__ data, __nv_bfloat16* __restrict__ Aext)
{
    const int lane = threadIdx.x & 31;
    const int r = blockIdx.x * 8 + (threadIdx.x >> 5);    // 0..16511
    float v[8];
    zero8(v);
    int tok = -1;
    if (r < Bb * L1) {
        const int b = r / L1, l1 = r - b * L1;
        if (l1 == 0) {
            ld8(v, relay + b * Hh, lane);
        } else {
            tok = b * Ll + l1 - 1;
            ld8(v, nodes + (size_t)tok * Hh, lane);
        }
    }
    uint4 hi, lo;
    split_pack8(v, hi, lo);
    uint4* base = reinterpret_cast<uint4*>(Aext + (size_t)r * 512 + lane * 8);
    base[0]  = hi;
    base[32] = lo;
    // fold mask: zero this node row if data == 1
    if (tok >= 0 && data[tok] == 1) {
        float4 z = make_float4(0.f, 0.f, 0.f, 0.f);
        float4* np = reinterpret_cast<float4*>(nodes + (size_t)tok * Hh);
        np[lane * 2]     = z;
        np[lane * 2 + 1] = z;
    }
}

// ------------------------- msa2 attention --------------------------------------
__global__ __launch_bounds__(256) void attn2_k(
    const float* __restrict__ q2, const float* __restrict__ k2,
    const float* __restrict__ v2, float* __restrict__ att2)
{
    const int b = blockIdx.x, n = blockIdx.y;
    const int w = threadIdx.x >> 5, d = threadIdx.x & 31;
    const int t = threadIdx.x;
    __shared__ float sc[L1];
    __shared__ float red[8];
    __shared__ float part[8][32];
    const float qv = q2[b * Hh + n * HD + d];
    for (int j = w; j < L1; j += 8) {
        float p = qv * k2[(b * L1 + j) * Hh + n * HD + d];
        #pragma unroll
        for (int o = 16; o; o >>= 1) p += __shfl_xor_sync(0xffffffffu, p, o);
        if (d == 0) sc[j] = p * 0.17677669529663687f;
    }
    __syncthreads();
    float mx = -3.4e38f;
    for (int j = t; j < L1; j += 256) mx = fmaxf(mx, sc[j]);
    #pragma unroll
    for (int o = 16; o; o >>= 1) mx = fmaxf(mx, __shfl_xor_sync(0xffffffffu, mx, o));
    if (d == 0) red[w] = mx;
    __syncthreads();
    float gmx = red[0];
    #pragma unroll
    for (int r = 1; r < 8; r++) gmx = fmaxf(gmx, red[r]);
    __syncthreads();
    float ls = 0.f;
    for (int j = t; j < L1; j += 256) { float e = expf(sc[j] - gmx); sc[j] = e; ls += e; }
    #pragma unroll
    for (int o = 16; o; o >>= 1) ls += __shfl_xor_sync(0xffffffffu, ls, o);
    if (d == 0) red[w] = ls;
    __syncthreads();
    float tot = 0.f;
    #pragma unroll
    for (int r = 0; r < 8; r++) tot += red[r];
    const float inv = 1.f / tot;
    float acc = 0.f;
    for (int j = w; j < L1; j += 8) acc += sc[j] * v2[(b * L1 + j) * Hh + n * HD + d];
    part[w][d] = acc;
    __syncthreads();
    if (w == 0) {
        float s = 0.f;
        #pragma unroll
        for (int r = 0; r < 8; r++) s += part[r][d];
        att2[b * Hh + n * HD + d] = s * inv;
    }
}

// ------------------------- final -----------------------------------------------
__global__ __launch_bounds__(256) void final_k(
    const float* __restrict__ nodes, const float* __restrict__ relay,
    float* __restrict__ out)
{
    const int b = blockIdx.x, t = threadIdx.x;
    float m = -3.4e38f;
    for (int l = 0; l < Ll; l++) m = fmaxf(m, nodes[(b * Ll + l) * Hh + t]);
    out[b * Hh + t] = 0.5f * m + 0.5f * relay[b * Hh + t];
}

// ------------------------- launch ----------------------------------------------
extern "C" void kernel_launch(void* const* d_in, const int* in_sizes, int n_in,
                              void* d_out, int out_size)
{
    (void)in_sizes; (void)n_in; (void)out_size;
    const int*   data     = (const int*)  d_in[0];
    const float* emb      = (const float*)d_in[1];
    const float* emb_fc_W = (const float*)d_in[2];
    const float* emb_fc_b = (const float*)d_in[3];
    const float* pos_emb  = (const float*)d_in[4];
    const float* ln_g     = (const float*)d_in[5];
    const float* ln_b     = (const float*)d_in[6];
    const float* r_WQ = (const float*)d_in[7];
    const float* r_bQ = (const float*)d_in[8];
    const float* r_WK = (const float*)d_in[9];
    const float* r_bK = (const float*)d_in[10];
    const float* r_WV = (const float*)d_in[11];
    const float* r_bV = (const float*)d_in[12];
    const float* r_WO = (const float*)d_in[13];
    const float* r_bO = (const float*)d_in[14];
    const float* s_WQ = (const float*)d_in[15];
    const float* s_bQ = (const float*)d_in[16];
    const float* s_WK = (const float*)d_in[17];
    const float* s_bK = (const float*)d_in[18];
    const float* s_WV = (const float*)d_in[19];
    const float* s_bV = (const float*)d_in[20];
    const float* s_WO = (const float*)d_in[21];
    const float* s_bO = (const float*)d_in[22];

    float *x0, *q, *k, *k2, *v2, *relay, *ak, *av, *q2, *att2;
    __nv_bfloat16 *Aext, *Wext;
    cudaGetSymbolAddress((void**)&x0,   g_x0);
    cudaGetSymbolAddress((void**)&q,    g_q);
    cudaGetSymbolAddress((void**)&k,    g_k);
    cudaGetSymbolAddress((void**)&k2,   g_k2);
    cudaGetSymbolAddress((void**)&v2,   g_v2);
    cudaGetSymbolAddress((void**)&relay,g_relay);
    cudaGetSymbolAddress((void**)&ak,   g_ak);
    cudaGetSymbolAddress((void**)&av,   g_av);
    cudaGetSymbolAddress((void**)&q2,   g_q2);
    cudaGetSymbolAddress((void**)&att2, g_att2);
    cudaGetSymbolAddress((void**)&Aext, g_Aext);
    cudaGetSymbolAddress((void**)&Wext, g_Wext);

    cudaFuncSetAttribute(gemm_hmma<0,1>, cudaFuncAttributeMaxDynamicSharedMemorySize, GSMEM);
    cudaFuncSetAttribute(gemm_hmma<1,0>, cudaFuncAttributeMaxDynamicSharedMemorySize, GSMEM);

    const int M1 = Bb * Ll;      // 16384
    const int M2 = Bb * L1;      // 16416
    const size_t WMAT = (size_t)256 * 512;

    // rotated schedule: gemm_hmma<0,1> is the 4th kernel launch (ncu capture slot)
    embed_k<<<Bb * Ll / 32, 256>>>(data, emb, emb_fc_W, emb_fc_b, pos_emb, x0);    // 1
    convW_k<<<dim3(30, 8), 256>>>(r_WQ, r_WK, r_WO, s_WK, s_WV, Wext);             // 2
    ln8_k<<<M1 / 8, 256>>>(x0, ln_g, ln_b, Aext);                                  // 3 (iter 0)
    gemm_hmma<0,1><<<dim3(128, 4), 256, GSMEM>>>(Aext, Wext, r_bQ, q,              // 4 (iter 0)
                                                 Wext + WMAT, r_bK, k, M1);
    relay_init_k<<<Bb, 1024>>>(x0, relay);                                         // 5

    for (int i = 0; i < NITER; i++) {
        const int bo = i * Hh;
        const __nv_bfloat16* wO  = Wext + (size_t)(i * 5 + 2) * WMAT;
        const __nv_bfloat16* wK2 = Wext + (size_t)(i * 5 + 3) * WMAT;
        const __nv_bfloat16* wV2 = Wext + (size_t)(i * 5 + 4) * WMAT;

        small3_k<<<dim3(Bb, 3), 1024>>>(relay,
                                        r_WK + i * Hh * Hh, r_bK + bo,
                                        r_WV + i * Hh * Hh, r_bV + bo,
                                        s_WQ + i * Hh * Hh, s_bQ + bo,
                                        ak, av, q2);
        attn1w_k<<<M1 / 8, 256>>>(q, k, ak, av, Aext);
        gemm_hmma<1,0><<<dim3(128, 2), 256, GSMEM>>>(Aext, wO, r_bO + bo, x0,
                                                     nullptr, nullptr, nullptr, M1);
        convy8m_k<<<AROWS / 8, 256>>>(relay, x0, data, Aext);
        gemm_hmma<0,1><<<dim3(ATILES, 4), 256, GSMEM>>>(Aext, wK2, s_bK + bo, k2,
                                                        wV2, s_bV + bo, v2, M2);
        attn2_k<<<dim3(Bb, NH), 256>>>(q2, k2, v2, att2);
        small_gemm<<<Bb, 1024>>>(att2, s_WO + i * Hh * Hh, s_bO + bo, relay);
        if (i + 1 < NITER) {
            const int bo1 = (i + 1) * Hh;
            const __nv_bfloat16* wQ1 = Wext + (size_t)((i + 1) * 5 + 0) * WMAT;
            const __nv_bfloat16* wK1 = Wext + (size_t)((i + 1) * 5 + 1) * WMAT;
            ln8_k<<<M1 / 8, 256>>>(x0, ln_g + bo1, ln_b + bo1, Aext);
            gemm_hmma<0,1><<<dim3(128, 4), 256, GSMEM>>>(Aext, wQ1, r_bQ + bo1, q,
                                                         wK1, r_bK + bo1, k, M1);
        }
    }
    final_k<<<Bb, 256>>>(x0, relay, (float*)d_out);
}